// round 1
// baseline (speedup 1.0000x reference)
#include <cuda_runtime.h>
#include <cuda_bf16.h>
#include <cstddef>

// Problem constants
#define Bb 4
#define Tt 4096
#define Din 1024
#define Hh 16
#define DKk 64
#define DVv 64
#define Mrows (Bb*Tt)          // 16384
#define NCOL 1024
#define KDIM 1024
#define EPSF 1e-6f

// ---------------- scratch (static device memory; no allocations allowed) ----
__device__ float g_Q[(size_t)Mrows * NCOL];
__device__ float g_K[(size_t)Mrows * NCOL];
__device__ float g_V[(size_t)Mrows * NCOL];
__device__ float g_attn[(size_t)Mrows * NCOL];
__device__ float g_kv[Bb * Hh * DVv * DKk];     // [b,h,dv,dk]
__device__ float g_ksum[Bb * Hh * DKk];         // [b,h,dk]

// ---------------- GEMM: C = act(A[M,K] @ W[K,N] + bias[N]) ------------------
// BM=128, BN=128, BK=16, 256 threads, 8x8 per-thread micro-tile.
#define BM 128
#define BN 128
#define BK 16
#define TM 8
#define TN 8
#define PAD_BM 132
#define PAD_BN 132

template<int ACT>
__global__ void __launch_bounds__(256) gemm_bias_act(
    const float* __restrict__ A, const float* __restrict__ W,
    const float* __restrict__ bias, float* __restrict__ C,
    int M, int N, int K)
{
    __shared__ float As[BK][PAD_BM];
    __shared__ float Ws[BK][PAD_BN];

    const int tid = threadIdx.x;
    const int bm = blockIdx.y * BM;
    const int bn = blockIdx.x * BN;

    // A loader: 128 rows x 16 cols. 512 float4 / 256 thr = 2 each.
    const int arow = tid >> 2;            // 0..63
    const int acol = (tid & 3) << 2;      // 0,4,8,12
    // W loader: 16 rows x 128 cols. 512 float4 / 256 thr = 2 each.
    const int wrow = tid >> 5;            // 0..7
    const int wcol = (tid & 31) << 2;     // 0..124

    const int tm = (tid >> 4) * TM;       // 0..120
    const int tn = (tid & 15) * TN;       // 0..120

    float acc[TM][TN];
#pragma unroll
    for (int i = 0; i < TM; i++)
#pragma unroll
        for (int j = 0; j < TN; j++) acc[i][j] = 0.f;

    for (int k0 = 0; k0 < K; k0 += BK) {
#pragma unroll
        for (int p = 0; p < 2; p++) {
            int r = arow + p * 64;
            float4 v = *(const float4*)&A[(size_t)(bm + r) * K + k0 + acol];
            As[acol + 0][r] = v.x;
            As[acol + 1][r] = v.y;
            As[acol + 2][r] = v.z;
            As[acol + 3][r] = v.w;
        }
#pragma unroll
        for (int p = 0; p < 2; p++) {
            int r = wrow + p * 8;
            *(float4*)&Ws[r][wcol] = *(const float4*)&W[(size_t)(k0 + r) * N + bn + wcol];
        }
        __syncthreads();

#pragma unroll
        for (int kk = 0; kk < BK; kk++) {
            float ra[TM], rb[TN];
            *(float4*)&ra[0] = *(const float4*)&As[kk][tm];
            *(float4*)&ra[4] = *(const float4*)&As[kk][tm + 4];
            *(float4*)&rb[0] = *(const float4*)&Ws[kk][tn];
            *(float4*)&rb[4] = *(const float4*)&Ws[kk][tn + 4];
#pragma unroll
            for (int i = 0; i < TM; i++)
#pragma unroll
                for (int j = 0; j < TN; j++)
                    acc[i][j] += ra[i] * rb[j];
        }
        __syncthreads();
    }

    // epilogue
    float bcol[TN];
#pragma unroll
    for (int j = 0; j < TN; j++) bcol[j] = bias[bn + tn + j];

#pragma unroll
    for (int i = 0; i < TM; i++) {
        const size_t row = (size_t)(bm + tm + i);
#pragma unroll
        for (int j = 0; j < TN; j += 4) {
            float4 o;
            o.x = acc[i][j + 0] + bcol[j + 0];
            o.y = acc[i][j + 1] + bcol[j + 1];
            o.z = acc[i][j + 2] + bcol[j + 2];
            o.w = acc[i][j + 3] + bcol[j + 3];
            if (ACT) {   // ELU(x)+1 = x>0 ? x+1 : exp(x)
                o.x = o.x > 0.f ? o.x + 1.f : __expf(o.x);
                o.y = o.y > 0.f ? o.y + 1.f : __expf(o.y);
                o.z = o.z > 0.f ? o.z + 1.f : __expf(o.z);
                o.w = o.w > 0.f ? o.w + 1.f : __expf(o.w);
            }
            *(float4*)&C[row * N + bn + tn + j] = o;
        }
    }
}

// ---------------- kv[b,h,dv,dk] = sum_t V[b,t,h,dv]*K[b,t,h,dk]; ksum -------
__global__ void __launch_bounds__(256) kv_kernel(
    const float* __restrict__ Kq, const float* __restrict__ Vq,
    float* __restrict__ kv, float* __restrict__ ksum)
{
    const int bh = blockIdx.x;           // 0..63
    const int b = bh >> 4, h = bh & 15;
    __shared__ float Ks[32][64];
    __shared__ float Vs[32][64];
    const int tid = threadIdx.x;
    const int ty = tid >> 4, tx = tid & 15;

    const float* Kbase = Kq + ((size_t)b * Tt) * NCOL + h * DKk;
    const float* Vbase = Vq + ((size_t)b * Tt) * NCOL + h * DVv;

    float acc[4][4];
#pragma unroll
    for (int i = 0; i < 4; i++)
#pragma unroll
        for (int j = 0; j < 4; j++) acc[i][j] = 0.f;
    float ks = 0.f;

    for (int t0 = 0; t0 < Tt; t0 += 32) {
#pragma unroll
        for (int p = 0; p < 2; p++) {
            int idx = tid + p * 256;      // 0..511
            int r = idx >> 4;             // 0..31
            int c = (idx & 15) << 2;      // 0..60
            *(float4*)&Ks[r][c] = *(const float4*)&Kbase[(size_t)(t0 + r) * NCOL + c];
            *(float4*)&Vs[r][c] = *(const float4*)&Vbase[(size_t)(t0 + r) * NCOL + c];
        }
        __syncthreads();
#pragma unroll 8
        for (int t = 0; t < 32; t++) {
            float rv[4], rk[4];
#pragma unroll
            for (int i = 0; i < 4; i++) rv[i] = Vs[t][ty * 4 + i];
#pragma unroll
            for (int j = 0; j < 4; j++) rk[j] = Ks[t][tx * 4 + j];
#pragma unroll
            for (int i = 0; i < 4; i++)
#pragma unroll
                for (int j = 0; j < 4; j++)
                    acc[i][j] += rv[i] * rk[j];
        }
        if (tid < 64) {
#pragma unroll
            for (int t = 0; t < 32; t++) ks += Ks[t][tid];
        }
        __syncthreads();
    }

    float* kvp = kv + (size_t)bh * (DVv * DKk);
#pragma unroll
    for (int i = 0; i < 4; i++) {
        float4 o;
        o.x = acc[i][0]; o.y = acc[i][1]; o.z = acc[i][2]; o.w = acc[i][3];
        *(float4*)&kvp[(ty * 4 + i) * DKk + tx * 4] = o;
    }
    if (tid < 64) ksum[bh * DKk + tid] = ks;
}

// ---------------- attn[b,t,h,dv] = norm(b,t,h) * sum_d Q[b,t,h,d]*kv[b,h,dv,d]
__global__ void __launch_bounds__(256) attn_kernel(
    const float* __restrict__ Qq, const float* __restrict__ kv,
    const float* __restrict__ ksum, float* __restrict__ attn)
{
    const int bh = blockIdx.x;            // 0..63
    const int b = bh >> 4, h = bh & 15;
    const int t0 = blockIdx.y * 64;       // 64 t-rows per block

    __shared__ float Qs[64][68];
    __shared__ float kvs[64][68];
    __shared__ float nrm[64];
    __shared__ float kss[64];

    const int tid = threadIdx.x;
    const float* Qbase = Qq + ((size_t)(b * Tt + t0)) * NCOL + h * DKk;

    // load Q tile 64x64 (1024 float4, 4/thread)
#pragma unroll
    for (int p = 0; p < 4; p++) {
        int idx = tid + p * 256;
        int r = idx >> 4;
        int c = (idx & 15) << 2;
        *(float4*)&Qs[r][c] = *(const float4*)&Qbase[(size_t)r * NCOL + c];
    }
    // load kv tile 64x64
    const float* kvb = kv + (size_t)bh * (DVv * DKk);
#pragma unroll
    for (int p = 0; p < 4; p++) {
        int idx = tid + p * 256;
        int r = idx >> 4;
        int c = (idx & 15) << 2;
        *(float4*)&kvs[r][c] = *(const float4*)&kvb[(size_t)r * DKk + c];
    }
    if (tid < 64) kss[tid] = ksum[bh * DKk + tid];
    __syncthreads();

    if (tid < 64) {
        float s = 0.f;
#pragma unroll
        for (int d = 0; d < 64; d++) s += Qs[tid][d] * kss[d];
        nrm[tid] = 1.f / (s + EPSF);
    }
    __syncthreads();

    const int tm = (tid >> 4) << 2;       // 0..60
    const int tn = (tid & 15) << 2;       // 0..60
    float acc[4][4];
#pragma unroll
    for (int i = 0; i < 4; i++)
#pragma unroll
        for (int j = 0; j < 4; j++) acc[i][j] = 0.f;

#pragma unroll 16
    for (int d = 0; d < 64; d++) {
        float rq[4], rk[4];
#pragma unroll
        for (int i = 0; i < 4; i++) rq[i] = Qs[tm + i][d];
#pragma unroll
        for (int j = 0; j < 4; j++) rk[j] = kvs[tn + j][d];
#pragma unroll
        for (int i = 0; i < 4; i++)
#pragma unroll
            for (int j = 0; j < 4; j++)
                acc[i][j] += rq[i] * rk[j];
    }

#pragma unroll
    for (int i = 0; i < 4; i++) {
        float nr = nrm[tm + i];
        float4 o;
        o.x = acc[i][0] * nr;
        o.y = acc[i][1] * nr;
        o.z = acc[i][2] * nr;
        o.w = acc[i][3] * nr;
        size_t row = (size_t)(b * Tt + t0 + tm + i);
        *(float4*)&attn[row * NCOL + h * DVv + tn] = o;
    }
}

// ---------------- launch -----------------------------------------------------
extern "C" void kernel_launch(void* const* d_in, const int* in_sizes, int n_in,
                              void* d_out, int out_size)
{
    (void)in_sizes; (void)n_in; (void)out_size;
    const float* query = (const float*)d_in[0];
    const float* key   = (const float*)d_in[1];
    const float* value = (const float*)d_in[2];
    const float* Wq    = (const float*)d_in[3];
    const float* bq    = (const float*)d_in[4];
    const float* Wk    = (const float*)d_in[5];
    const float* bk    = (const float*)d_in[6];
    const float* Wv    = (const float*)d_in[7];
    const float* bv    = (const float*)d_in[8];
    const float* Wo    = (const float*)d_in[9];
    const float* bo    = (const float*)d_in[10];
    float* out = (float*)d_out;

    float *Qp, *Kp, *Vp, *Ap, *kvp, *ksp;
    cudaGetSymbolAddress((void**)&Qp,  g_Q);
    cudaGetSymbolAddress((void**)&Kp,  g_K);
    cudaGetSymbolAddress((void**)&Vp,  g_V);
    cudaGetSymbolAddress((void**)&Ap,  g_attn);
    cudaGetSymbolAddress((void**)&kvp, g_kv);
    cudaGetSymbolAddress((void**)&ksp, g_ksum);

    dim3 blk(256);
    dim3 grd(NCOL / BN, Mrows / BM);   // (8, 128)

    gemm_bias_act<1><<<grd, blk>>>(query, Wq, bq, Qp, Mrows, NCOL, KDIM);
    gemm_bias_act<1><<<grd, blk>>>(key,   Wk, bk, Kp, Mrows, NCOL, KDIM);
    gemm_bias_act<0><<<grd, blk>>>(value, Wv, bv, Vp, Mrows, NCOL, KDIM);

    kv_kernel<<<Bb * Hh, 256>>>(Kp, Vp, kvp, ksp);
    attn_kernel<<<dim3(Bb * Hh, Tt / 64), 256>>>(Qp, kvp, ksp, Ap);

    gemm_bias_act<0><<<grd, blk>>>(Ap, Wo, bo, out, Mrows, NCOL, KDIM);
}

// round 3
// speedup vs baseline: 1.9093x; 1.9093x over previous
#include <cuda_runtime.h>
#include <cuda_bf16.h>
#include <cstdint>
#include <cstddef>

#define Bb 4
#define Tt 4096
#define Hh 16
#define DKk 64
#define DVv 64
#define Mrows (Bb*Tt)          // 16384
#define NCOL 1024
#define KDIM 1024
#define EPSF 1e-6f

// ---------------- static scratch ----------------
__device__ float g_Q[(size_t)Mrows*NCOL];
__device__ float g_K[(size_t)Mrows*NCOL];
__device__ float g_V[(size_t)Mrows*NCOL];
__device__ __nv_bfloat16 g_Ahi[(size_t)Mrows*KDIM];
__device__ __nv_bfloat16 g_Alo[(size_t)Mrows*KDIM];
__device__ __nv_bfloat16 g_Whi[4][(size_t)NCOL*KDIM];   // transposed [N,K]
__device__ __nv_bfloat16 g_Wlo[4][(size_t)NCOL*KDIM];
__device__ float g_kvp[8*64*DVv*DKk];
__device__ float g_ksp[8*64*DKk];
__device__ float g_kv[64*DVv*DKk];
__device__ float g_ksum[64*DKk];

// ---------------- PTX helpers (baseline ISA only: sm_80/90 features) --------
__device__ __forceinline__ uint32_t s2u(const void* p){
    uint32_t a;
    asm("{ .reg .u64 t; cvta.to.shared.u64 t, %1; cvt.u32.u64 %0, t; }" : "=r"(a) : "l"(p));
    return a;
}
__device__ __forceinline__ void cpa16(uint32_t dst, const void* src){
    asm volatile("cp.async.cg.shared.global [%0], [%1], 16;" :: "r"(dst), "l"(src) : "memory");
}
__device__ __forceinline__ void cp_commit(){
    asm volatile("cp.async.commit_group;" ::: "memory");
}
__device__ __forceinline__ void cp_wait1(){
    asm volatile("cp.async.wait_group 1;" ::: "memory");
}
__device__ __forceinline__ void ldm4(uint32_t* r, uint32_t addr){
    asm volatile("ldmatrix.sync.aligned.m8n8.x4.shared.b16 {%0,%1,%2,%3}, [%4];"
        : "=r"(r[0]), "=r"(r[1]), "=r"(r[2]), "=r"(r[3]) : "r"(addr));
}
__device__ __forceinline__ void mma16816(float* c, const uint32_t* a, uint32_t b0, uint32_t b1){
    asm volatile("mma.sync.aligned.m16n8k16.row.col.f32.bf16.bf16.f32 "
        "{%0,%1,%2,%3}, {%4,%5,%6,%7}, {%8,%9}, {%0,%1,%2,%3};"
        : "+f"(c[0]), "+f"(c[1]), "+f"(c[2]), "+f"(c[3])
        : "r"(a[0]), "r"(a[1]), "r"(a[2]), "r"(a[3]), "r"(b0), "r"(b1));
}

// ---------------- HMMA GEMM: C = act(A[M,K] @ W[N,K]^T + bias) --------------
// Tile 128x128, k-chunk 32, 3-stage cp.async pipeline, bf16x3 split accum.
#define RSTRIDE 80                 // bytes per 32-bf16 row (16B pad: conflict-free ldmatrix)
#define TILE_SM (128*RSTRIDE)      // 10240 bytes per [128][32] tile
#define STG (4*TILE_SM)            // Ahi,Alo,Whi,Wlo per stage = 40960
#define NST 3
#define SMEM_SZ (NST*STG)          // 122880
#define NKCH (KDIM/32)             // 32 k-chunks

template<int ACT>
__global__ void __launch_bounds__(256, 1) gemm_mma(
    const __nv_bfloat16* __restrict__ Ahi, const __nv_bfloat16* __restrict__ Alo,
    const __nv_bfloat16* __restrict__ Whi, const __nv_bfloat16* __restrict__ Wlo,
    const float* __restrict__ bias, float* __restrict__ C)
{
    extern __shared__ __align__(128) char smem[];
    const uint32_t sb = s2u(smem);
    const int tid  = threadIdx.x;
    const int warp = tid >> 5, lane = tid & 31;
    const int wm = warp & 3, wn = warp >> 2;       // warp tile: 32(m) x 64(n)
    const int bm = blockIdx.y * 128, bn = blockIdx.x * 128;

    // loader coords: each thread brings 2x16B (32B contiguous) per tile
    const int lrow = tid >> 1;          // 0..127
    const int lc   = (tid & 1) * 2;     // chunk 0 or 2

    const __nv_bfloat16* gA0 = Ahi + (size_t)(bm + lrow) * KDIM + lc * 8;
    const __nv_bfloat16* gA1 = Alo + (size_t)(bm + lrow) * KDIM + lc * 8;
    const __nv_bfloat16* gB0 = Whi + (size_t)(bn + lrow) * KDIM + lc * 8;
    const __nv_bfloat16* gB1 = Wlo + (size_t)(bn + lrow) * KDIM + lc * 8;
    const uint32_t dofs = lrow * RSTRIDE + lc * 16;

    float acc[2][8][4];
#pragma unroll
    for (int i = 0; i < 2; i++)
#pragma unroll
        for (int j = 0; j < 8; j++)
#pragma unroll
            for (int q = 0; q < 4; q++) acc[i][j][q] = 0.f;

#define ISSUE(kt, s) do {                                   \
        uint32_t st_ = sb + (s) * STG + dofs;               \
        int ko_ = (kt) * 32;                                \
        cpa16(st_,                 gA0 + ko_);              \
        cpa16(st_ + 16,            gA0 + ko_ + 8);          \
        cpa16(st_ +   TILE_SM,     gA1 + ko_);              \
        cpa16(st_ +   TILE_SM + 16,gA1 + ko_ + 8);          \
        cpa16(st_ + 2*TILE_SM,     gB0 + ko_);              \
        cpa16(st_ + 2*TILE_SM + 16,gB0 + ko_ + 8);          \
        cpa16(st_ + 3*TILE_SM,     gB1 + ko_);              \
        cpa16(st_ + 3*TILE_SM + 16,gB1 + ko_ + 8);          \
    } while (0)

    ISSUE(0, 0); cp_commit();
    ISSUE(1, 1); cp_commit();

    const int lm = lane & 15, lh = lane >> 4;

    for (int kt = 0; kt < NKCH; kt++) {
        cp_wait1();
        __syncthreads();
        if (kt + 2 < NKCH) ISSUE(kt + 2, (kt + 2) % NST);
        cp_commit();

        const uint32_t st = sb + (kt % NST) * STG;
#pragma unroll
        for (int kk = 0; kk < 2; kk++) {
            const uint32_t kcol = kk * 32 + lh * 16;
            uint32_t ah[2][4], al[2][4], bh[4][4], bl[4][4];
#pragma unroll
            for (int mt = 0; mt < 2; mt++) {
                uint32_t r = (uint32_t)(wm * 32 + mt * 16 + lm);
                ldm4(ah[mt], st + r * RSTRIDE + kcol);
                ldm4(al[mt], st + TILE_SM + r * RSTRIDE + kcol);
            }
#pragma unroll
            for (int g = 0; g < 4; g++) {
                uint32_t r = (uint32_t)(wn * 64 + g * 16 + lm);
                ldm4(bh[g], st + 2 * TILE_SM + r * RSTRIDE + kcol);
                ldm4(bl[g], st + 3 * TILE_SM + r * RSTRIDE + kcol);
            }
            // pass 1: hi*hi
#pragma unroll
            for (int mt = 0; mt < 2; mt++)
#pragma unroll
                for (int g = 0; g < 4; g++) {
                    mma16816(acc[mt][2*g],   ah[mt], bh[g][0], bh[g][2]);
                    mma16816(acc[mt][2*g+1], ah[mt], bh[g][1], bh[g][3]);
                }
            // pass 2: hi*lo
#pragma unroll
            for (int mt = 0; mt < 2; mt++)
#pragma unroll
                for (int g = 0; g < 4; g++) {
                    mma16816(acc[mt][2*g],   ah[mt], bl[g][0], bl[g][2]);
                    mma16816(acc[mt][2*g+1], ah[mt], bl[g][1], bl[g][3]);
                }
            // pass 3: lo*hi
#pragma unroll
            for (int mt = 0; mt < 2; mt++)
#pragma unroll
                for (int g = 0; g < 4; g++) {
                    mma16816(acc[mt][2*g],   al[mt], bh[g][0], bh[g][2]);
                    mma16816(acc[mt][2*g+1], al[mt], bh[g][1], bh[g][3]);
                }
        }
    }
#undef ISSUE

    // epilogue: direct stores with bias (+ optional ELU+1)
#pragma unroll
    for (int mt = 0; mt < 2; mt++) {
        const int row0 = bm + wm * 32 + mt * 16 + (lane >> 2);
#pragma unroll
        for (int ng = 0; ng < 8; ng++) {
            const int col = bn + wn * 64 + ng * 8 + 2 * (lane & 3);
            const float b0 = bias[col], b1 = bias[col + 1];
            float2 v0, v1;
            v0.x = acc[mt][ng][0] + b0;  v0.y = acc[mt][ng][1] + b1;
            v1.x = acc[mt][ng][2] + b0;  v1.y = acc[mt][ng][3] + b1;
            if (ACT) {
                v0.x = v0.x > 0.f ? v0.x + 1.f : __expf(v0.x);
                v0.y = v0.y > 0.f ? v0.y + 1.f : __expf(v0.y);
                v1.x = v1.x > 0.f ? v1.x + 1.f : __expf(v1.x);
                v1.y = v1.y > 0.f ? v1.y + 1.f : __expf(v1.y);
            }
            *(float2*)&C[(size_t)row0 * NCOL + col]       = v0;
            *(float2*)&C[(size_t)(row0 + 8) * NCOL + col] = v1;
        }
    }
}

// ---------------- fp32 -> bf16 hi/lo split (activations) ----------------
__global__ void __launch_bounds__(256) asplit(const float* __restrict__ x,
                                              __nv_bfloat16* __restrict__ hi,
                                              __nv_bfloat16* __restrict__ lo, int n4)
{
    int i = blockIdx.x * 256 + threadIdx.x;
    if (i >= n4) return;
    float4 v = ((const float4*)x)[i];
    __nv_bfloat16 h0 = __float2bfloat16(v.x), h1 = __float2bfloat16(v.y);
    __nv_bfloat16 h2 = __float2bfloat16(v.z), h3 = __float2bfloat16(v.w);
    __nv_bfloat162* H = (__nv_bfloat162*)hi;
    __nv_bfloat162* L = (__nv_bfloat162*)lo;
    H[2*i]   = __halves2bfloat162(h0, h1);
    H[2*i+1] = __halves2bfloat162(h2, h3);
    L[2*i]   = __halves2bfloat162(__float2bfloat16(v.x - __bfloat162float(h0)),
                                  __float2bfloat16(v.y - __bfloat162float(h1)));
    L[2*i+1] = __halves2bfloat162(__float2bfloat16(v.z - __bfloat162float(h2)),
                                  __float2bfloat16(v.w - __bfloat162float(h3)));
}

// ---------------- weight transpose + split: W[K,N] -> Wt_hi/lo[N,K] ---------
__global__ void __launch_bounds__(256) wsplit(const float* __restrict__ W,
                                              __nv_bfloat16* __restrict__ thi,
                                              __nv_bfloat16* __restrict__ tlo)
{
    __shared__ float tile[32][33];
    const int n0 = blockIdx.x * 32, k0 = blockIdx.y * 32;
    const int tx = threadIdx.x & 31, ty = threadIdx.x >> 5;
#pragma unroll
    for (int r = ty; r < 32; r += 8)
        tile[r][tx] = W[(size_t)(k0 + r) * NCOL + n0 + tx];
    __syncthreads();
#pragma unroll
    for (int r = ty; r < 32; r += 8) {
        float v = tile[tx][r];   // = W[k0+tx][n0+r]
        __nv_bfloat16 hh = __float2bfloat16(v);
        thi[(size_t)(n0 + r) * KDIM + k0 + tx] = hh;
        tlo[(size_t)(n0 + r) * KDIM + k0 + tx] = __float2bfloat16(v - __bfloat162float(hh));
    }
}

// ---------------- kv partial: per (bh, split of 512 t-rows) -----------------
__global__ void __launch_bounds__(256) kv_partial(const float* __restrict__ Kq, const float* __restrict__ Vq,
                                                  float* __restrict__ kvp, float* __restrict__ ksp)
{
    const int bh = blockIdx.x, sp = blockIdx.y;
    const int b = bh >> 4, hd = bh & 15;
    __shared__ float Ks[32][64];
    __shared__ float Vs[32][64];
    const int tid = threadIdx.x;
    const int ty = tid >> 4, tx = tid & 15;
    const float* Kb = Kq + ((size_t)b * Tt + sp * 512) * NCOL + hd * DKk;
    const float* Vb = Vq + ((size_t)b * Tt + sp * 512) * NCOL + hd * DVv;

    float acc[4][4];
#pragma unroll
    for (int i = 0; i < 4; i++)
#pragma unroll
        for (int j = 0; j < 4; j++) acc[i][j] = 0.f;
    float ks = 0.f;

    for (int t0 = 0; t0 < 512; t0 += 32) {
#pragma unroll
        for (int p = 0; p < 2; p++) {
            int idx = tid + p * 256;
            int r = idx >> 4, c = (idx & 15) << 2;
            *(float4*)&Ks[r][c] = *(const float4*)&Kb[(size_t)(t0 + r) * NCOL + c];
            *(float4*)&Vs[r][c] = *(const float4*)&Vb[(size_t)(t0 + r) * NCOL + c];
        }
        __syncthreads();
#pragma unroll 8
        for (int t = 0; t < 32; t++) {
            float rv[4], rk[4];
#pragma unroll
            for (int i = 0; i < 4; i++) rv[i] = Vs[t][ty * 4 + i];
#pragma unroll
            for (int j = 0; j < 4; j++) rk[j] = Ks[t][tx * 4 + j];
#pragma unroll
            for (int i = 0; i < 4; i++)
#pragma unroll
                for (int j = 0; j < 4; j++)
                    acc[i][j] += rv[i] * rk[j];
        }
        if (tid < 64) {
#pragma unroll
            for (int t = 0; t < 32; t++) ks += Ks[t][tid];
        }
        __syncthreads();
    }

    float* o = kvp + (size_t)(sp * 64 + bh) * (DVv * DKk);
#pragma unroll
    for (int i = 0; i < 4; i++) {
        float4 v;
        v.x = acc[i][0]; v.y = acc[i][1]; v.z = acc[i][2]; v.w = acc[i][3];
        *(float4*)&o[(ty * 4 + i) * DKk + tx * 4] = v;
    }
    if (tid < 64) ksp[(sp * 64 + bh) * DKk + tid] = ks;
}

__global__ void __launch_bounds__(256) kv_reduce(const float* __restrict__ kvp, const float* __restrict__ ksp,
                                                 float* __restrict__ kv, float* __restrict__ ksum)
{
    const int bh = blockIdx.x, tid = threadIdx.x;
    for (int i = tid; i < DVv * DKk; i += 256) {
        float s = 0.f;
#pragma unroll
        for (int y = 0; y < 8; y++) s += kvp[(size_t)(y * 64 + bh) * (DVv * DKk) + i];
        kv[(size_t)bh * (DVv * DKk) + i] = s;
    }
    if (tid < DKk) {
        float s = 0.f;
#pragma unroll
        for (int y = 0; y < 8; y++) s += ksp[(y * 64 + bh) * DKk + tid];
        ksum[bh * DKk + tid] = s;
    }
}

// ---------------- attn: writes bf16 hi/lo directly (final GEMM input) -------
__global__ void __launch_bounds__(256) attn_tc(
    const float* __restrict__ Qq, const float* __restrict__ kv,
    const float* __restrict__ ksum,
    __nv_bfloat16* __restrict__ ahi, __nv_bfloat16* __restrict__ alo)
{
    const int bh = blockIdx.x;
    const int b = bh >> 4, hd = bh & 15;
    const int t0 = blockIdx.y * 64;

    __shared__ float Qs[64][68];
    __shared__ float kvs[64][68];
    __shared__ float nrm[64];
    __shared__ float kss[64];

    const int tid = threadIdx.x;
    const float* Qbase = Qq + ((size_t)(b * Tt + t0)) * NCOL + hd * DKk;

#pragma unroll
    for (int p = 0; p < 4; p++) {
        int idx = tid + p * 256;
        int r = idx >> 4, c = (idx & 15) << 2;
        *(float4*)&Qs[r][c] = *(const float4*)&Qbase[(size_t)r * NCOL + c];
    }
    const float* kvb = kv + (size_t)bh * (DVv * DKk);
#pragma unroll
    for (int p = 0; p < 4; p++) {
        int idx = tid + p * 256;
        int r = idx >> 4, c = (idx & 15) << 2;
        *(float4*)&kvs[r][c] = *(const float4*)&kvb[(size_t)r * DKk + c];
    }
    if (tid < 64) kss[tid] = ksum[bh * DKk + tid];
    __syncthreads();

    if (tid < 64) {
        float s = 0.f;
#pragma unroll
        for (int d = 0; d < 64; d++) s += Qs[tid][d] * kss[d];
        nrm[tid] = 1.f / (s + EPSF);
    }
    __syncthreads();

    const int tm = (tid >> 4) << 2;
    const int tn = (tid & 15) << 2;
    float acc[4][4];
#pragma unroll
    for (int i = 0; i < 4; i++)
#pragma unroll
        for (int j = 0; j < 4; j++) acc[i][j] = 0.f;

#pragma unroll 16
    for (int d = 0; d < 64; d++) {
        float rq[4], rk[4];
#pragma unroll
        for (int i = 0; i < 4; i++) rq[i] = Qs[tm + i][d];
#pragma unroll
        for (int j = 0; j < 4; j++) rk[j] = kvs[tn + j][d];
#pragma unroll
        for (int i = 0; i < 4; i++)
#pragma unroll
            for (int j = 0; j < 4; j++)
                acc[i][j] += rq[i] * rk[j];
    }

#pragma unroll
    for (int i = 0; i < 4; i++) {
        float nr = nrm[tm + i];
        size_t base = ((size_t)(b * Tt + t0 + tm + i)) * NCOL + hd * DVv + tn;
        float v0 = acc[i][0] * nr, v1 = acc[i][1] * nr, v2 = acc[i][2] * nr, v3 = acc[i][3] * nr;
        __nv_bfloat16 a0 = __float2bfloat16(v0), a1 = __float2bfloat16(v1);
        __nv_bfloat16 a2 = __float2bfloat16(v2), a3 = __float2bfloat16(v3);
        ((__nv_bfloat162*)(ahi + base))[0] = __halves2bfloat162(a0, a1);
        ((__nv_bfloat162*)(ahi + base))[1] = __halves2bfloat162(a2, a3);
        ((__nv_bfloat162*)(alo + base))[0] = __halves2bfloat162(
            __float2bfloat16(v0 - __bfloat162float(a0)), __float2bfloat16(v1 - __bfloat162float(a1)));
        ((__nv_bfloat162*)(alo + base))[1] = __halves2bfloat162(
            __float2bfloat16(v2 - __bfloat162float(a2)), __float2bfloat16(v3 - __bfloat162float(a3)));
    }
}

// ---------------- host ----------------
extern "C" void kernel_launch(void* const* d_in, const int* in_sizes, int n_in,
                              void* d_out, int out_size)
{
    (void)in_sizes; (void)n_in; (void)out_size;
    const float* query = (const float*)d_in[0];
    const float* key   = (const float*)d_in[1];
    const float* value = (const float*)d_in[2];
    const float* Wq    = (const float*)d_in[3];
    const float* bq    = (const float*)d_in[4];
    const float* Wk    = (const float*)d_in[5];
    const float* bk    = (const float*)d_in[6];
    const float* Wv    = (const float*)d_in[7];
    const float* bv    = (const float*)d_in[8];
    const float* Wo    = (const float*)d_in[9];
    const float* bo    = (const float*)d_in[10];
    float* out = (float*)d_out;

    float *Qp, *Kp, *Vp, *kvpp, *kspp, *kvv, *kss;
    __nv_bfloat16 *Ahi, *Alo, *WhiP, *WloP;
    cudaGetSymbolAddress((void**)&Qp,   g_Q);
    cudaGetSymbolAddress((void**)&Kp,   g_K);
    cudaGetSymbolAddress((void**)&Vp,   g_V);
    cudaGetSymbolAddress((void**)&Ahi,  g_Ahi);
    cudaGetSymbolAddress((void**)&Alo,  g_Alo);
    cudaGetSymbolAddress((void**)&WhiP, g_Whi);
    cudaGetSymbolAddress((void**)&WloP, g_Wlo);
    cudaGetSymbolAddress((void**)&kvpp, g_kvp);
    cudaGetSymbolAddress((void**)&kspp, g_ksp);
    cudaGetSymbolAddress((void**)&kvv,  g_kv);
    cudaGetSymbolAddress((void**)&kss,  g_ksum);

    cudaFuncSetAttribute(gemm_mma<0>, cudaFuncAttributeMaxDynamicSharedMemorySize, SMEM_SZ);
    cudaFuncSetAttribute(gemm_mma<1>, cudaFuncAttributeMaxDynamicSharedMemorySize, SMEM_SZ);

    const size_t WSZ = (size_t)NCOL * KDIM;

    // weight prep (transpose + hi/lo split)
    dim3 wgrid(NCOL / 32, KDIM / 32);
    wsplit<<<wgrid, 256>>>(Wq, WhiP + 0 * WSZ, WloP + 0 * WSZ);
    wsplit<<<wgrid, 256>>>(Wk, WhiP + 1 * WSZ, WloP + 1 * WSZ);
    wsplit<<<wgrid, 256>>>(Wv, WhiP + 2 * WSZ, WloP + 2 * WSZ);
    wsplit<<<wgrid, 256>>>(Wo, WhiP + 3 * WSZ, WloP + 3 * WSZ);

    const int n4 = Mrows * KDIM / 4;
    dim3 ggrid(NCOL / 128, Mrows / 128);   // (8, 128)

    asplit<<<n4 / 256, 256>>>(query, Ahi, Alo, n4);
    gemm_mma<1><<<ggrid, 256, SMEM_SZ>>>(Ahi, Alo, WhiP + 0 * WSZ, WloP + 0 * WSZ, bq, Qp);
    asplit<<<n4 / 256, 256>>>(key, Ahi, Alo, n4);
    gemm_mma<1><<<ggrid, 256, SMEM_SZ>>>(Ahi, Alo, WhiP + 1 * WSZ, WloP + 1 * WSZ, bk, Kp);
    asplit<<<n4 / 256, 256>>>(value, Ahi, Alo, n4);
    gemm_mma<0><<<ggrid, 256, SMEM_SZ>>>(Ahi, Alo, WhiP + 2 * WSZ, WloP + 2 * WSZ, bv, Vp);

    kv_partial<<<dim3(64, 8), 256>>>(Kp, Vp, kvpp, kspp);
    kv_reduce<<<64, 256>>>(kvpp, kspp, kvv, kss);
    attn_tc<<<dim3(64, Tt / 64), 256>>>(Qp, kvv, kss, Ahi, Alo);

    gemm_mma<0><<<ggrid, 256, SMEM_SZ>>>(Ahi, Alo, WhiP + 3 * WSZ, WloP + 3 * WSZ, bo, out);
}

// round 4
// speedup vs baseline: 2.3500x; 1.2308x over previous
#include <cuda_runtime.h>
#include <cuda_fp16.h>
#include <cstdint>
#include <cstddef>

#define Bb 4
#define Tt 4096
#define Hh 16
#define DKk 64
#define DVv 64
#define Mrows (Bb*Tt)          // 16384
#define NCOL 1024
#define KDIM 1024
#define EPSF 1e-6f

// ---------------- static scratch ----------------
__device__ float g_Q[(size_t)Mrows*NCOL];
__device__ float g_K[(size_t)Mrows*NCOL];
__device__ float g_V[(size_t)Mrows*NCOL];
__device__ __half g_Ahi[(size_t)Mrows*KDIM];
__device__ __half g_Alo[(size_t)Mrows*KDIM];
__device__ __half g_Whi[4][(size_t)NCOL*KDIM];   // transposed [N,K]
__device__ __half g_Wlo[4][(size_t)NCOL*KDIM];
__device__ float g_kvp[8*64*DVv*DKk];
__device__ float g_ksp[8*64*DKk];
__device__ float g_kv[64*DVv*DKk];
__device__ float g_ksum[64*DKk];

// ---------------- PTX helpers (baseline ISA: sm_80 features only) -----------
__device__ __forceinline__ uint32_t s2u(const void* p){
    uint32_t a;
    asm("{ .reg .u64 t; cvta.to.shared.u64 t, %1; cvt.u32.u64 %0, t; }" : "=r"(a) : "l"(p));
    return a;
}
__device__ __forceinline__ void cpa16(uint32_t dst, const void* src){
    asm volatile("cp.async.cg.shared.global [%0], [%1], 16;" :: "r"(dst), "l"(src) : "memory");
}
__device__ __forceinline__ void cp_commit(){
    asm volatile("cp.async.commit_group;" ::: "memory");
}
template<int N>
__device__ __forceinline__ void cp_waitg(){
    asm volatile("cp.async.wait_group %0;" :: "n"(N) : "memory");
}
__device__ __forceinline__ void ldm4(uint32_t* r, uint32_t addr){
    asm volatile("ldmatrix.sync.aligned.m8n8.x4.shared.b16 {%0,%1,%2,%3}, [%4];"
        : "=r"(r[0]), "=r"(r[1]), "=r"(r[2]), "=r"(r[3]) : "r"(addr));
}
__device__ __forceinline__ void mma16816(float* c, const uint32_t* a, uint32_t b0, uint32_t b1){
    asm volatile("mma.sync.aligned.m16n8k16.row.col.f32.f16.f16.f32 "
        "{%0,%1,%2,%3}, {%4,%5,%6,%7}, {%8,%9}, {%0,%1,%2,%3};"
        : "+f"(c[0]), "+f"(c[1]), "+f"(c[2]), "+f"(c[3])
        : "r"(a[0]), "r"(a[1]), "r"(a[2]), "r"(a[3]), "r"(b0), "r"(b1));
}

// ---------------- HMMA GEMM: C = act(A[M,K] @ W[N,K]^T + bias) --------------
// Tile 128x128, k-chunk 32, cp.async pipeline, fp16 split accumulation.
// NPASS=2: C = (Ahi+Alo)*Bhi   (3 smem tiles/stage, 4 stages)
// NPASS=3: C = Ahi*Bhi + Ahi*Blo + Alo*Bhi (4 tiles/stage, 3 stages)
#define RSTRIDE 80                 // bytes per 32-half row (16B pad: conflict-free ldmatrix)
#define TILE_SM (128*RSTRIDE)      // 10240 bytes per [128][32] tile
#define NKCH (KDIM/32)             // 32 k-chunks

template<int ACT, int NPASS>
__global__ void __launch_bounds__(256, 1) gemm_mma(
    const __half* __restrict__ Ahi, const __half* __restrict__ Alo,
    const __half* __restrict__ Whi, const __half* __restrict__ Wlo,
    const float* __restrict__ bias, float* __restrict__ C)
{
    constexpr int NTILE = (NPASS == 3) ? 4 : 3;
    constexpr int STGB  = NTILE * TILE_SM;       // bytes per stage
    constexpr int NSTG  = (NPASS == 3) ? 3 : 4;  // pipeline depth (both = 120KB smem)

    extern __shared__ __align__(128) char smem[];
    const uint32_t sb = s2u(smem);
    const int tid  = threadIdx.x;
    const int warp = tid >> 5, lane = tid & 31;
    const int wm = warp & 3, wn = warp >> 2;       // warp tile: 32(m) x 64(n)
    const int bm = blockIdx.y * 128, bn = blockIdx.x * 128;

    // loader coords: each thread brings 2x16B (32B contiguous) per tile
    const int lrow = tid >> 1;          // 0..127
    const int lc   = (tid & 1) * 2;     // chunk 0 or 2

    const __half* gA0 = Ahi + (size_t)(bm + lrow) * KDIM + lc * 8;
    const __half* gA1 = Alo + (size_t)(bm + lrow) * KDIM + lc * 8;
    const __half* gB0 = Whi + (size_t)(bn + lrow) * KDIM + lc * 8;
    const __half* gB1 = Wlo + (size_t)(bn + lrow) * KDIM + lc * 8;
    const uint32_t dofs = lrow * RSTRIDE + lc * 16;

    float acc[2][8][4];
#pragma unroll
    for (int i = 0; i < 2; i++)
#pragma unroll
        for (int j = 0; j < 8; j++)
#pragma unroll
            for (int q = 0; q < 4; q++) acc[i][j][q] = 0.f;

#define ISSUE(kt, s) do {                                   \
        uint32_t st_ = sb + (s) * STGB + dofs;              \
        int ko_ = (kt) * 32;                                \
        cpa16(st_,                  gA0 + ko_);             \
        cpa16(st_ + 16,             gA0 + ko_ + 8);         \
        cpa16(st_ +   TILE_SM,      gA1 + ko_);             \
        cpa16(st_ +   TILE_SM + 16, gA1 + ko_ + 8);         \
        cpa16(st_ + 2*TILE_SM,      gB0 + ko_);             \
        cpa16(st_ + 2*TILE_SM + 16, gB0 + ko_ + 8);         \
        if (NPASS == 3) {                                   \
            cpa16(st_ + 3*TILE_SM,      gB1 + ko_);         \
            cpa16(st_ + 3*TILE_SM + 16, gB1 + ko_ + 8);     \
        }                                                   \
    } while (0)

#pragma unroll
    for (int s = 0; s < NSTG - 1; s++) { ISSUE(s, s); cp_commit(); }

    const int lm = lane & 15, lh = lane >> 4;

    for (int kt = 0; kt < NKCH; kt++) {
        cp_waitg<NSTG - 2>();
        __syncthreads();
        if (kt + NSTG - 1 < NKCH) ISSUE(kt + NSTG - 1, (kt + NSTG - 1) % NSTG);
        cp_commit();

        const uint32_t st = sb + (kt % NSTG) * STGB;
#pragma unroll
        for (int kk = 0; kk < 2; kk++) {
            const uint32_t kcol = kk * 32 + lh * 16;
            uint32_t ah[2][4], al[2][4], bh[4][4], bl[4][4];
#pragma unroll
            for (int mt = 0; mt < 2; mt++) {
                uint32_t r = (uint32_t)(wm * 32 + mt * 16 + lm);
                ldm4(ah[mt], st + r * RSTRIDE + kcol);
                ldm4(al[mt], st + TILE_SM + r * RSTRIDE + kcol);
            }
#pragma unroll
            for (int g = 0; g < 4; g++) {
                uint32_t r = (uint32_t)(wn * 64 + g * 16 + lm);
                ldm4(bh[g], st + 2 * TILE_SM + r * RSTRIDE + kcol);
                if (NPASS == 3)
                    ldm4(bl[g], st + 3 * TILE_SM + r * RSTRIDE + kcol);
            }
            // pass 1: Ahi * Bhi
#pragma unroll
            for (int mt = 0; mt < 2; mt++)
#pragma unroll
                for (int g = 0; g < 4; g++) {
                    mma16816(acc[mt][2*g],   ah[mt], bh[g][0], bh[g][2]);
                    mma16816(acc[mt][2*g+1], ah[mt], bh[g][1], bh[g][3]);
                }
            // pass 2: Alo * Bhi
#pragma unroll
            for (int mt = 0; mt < 2; mt++)
#pragma unroll
                for (int g = 0; g < 4; g++) {
                    mma16816(acc[mt][2*g],   al[mt], bh[g][0], bh[g][2]);
                    mma16816(acc[mt][2*g+1], al[mt], bh[g][1], bh[g][3]);
                }
            // pass 3: Ahi * Blo (only NPASS==3)
            if (NPASS == 3) {
#pragma unroll
                for (int mt = 0; mt < 2; mt++)
#pragma unroll
                    for (int g = 0; g < 4; g++) {
                        mma16816(acc[mt][2*g],   ah[mt], bl[g][0], bl[g][2]);
                        mma16816(acc[mt][2*g+1], ah[mt], bl[g][1], bl[g][3]);
                    }
            }
        }
    }
#undef ISSUE

    // epilogue: direct stores with bias (+ optional ELU+1)
#pragma unroll
    for (int mt = 0; mt < 2; mt++) {
        const int row0 = bm + wm * 32 + mt * 16 + (lane >> 2);
#pragma unroll
        for (int ng = 0; ng < 8; ng++) {
            const int col = bn + wn * 64 + ng * 8 + 2 * (lane & 3);
            const float b0 = bias[col], b1 = bias[col + 1];
            float2 v0, v1;
            v0.x = acc[mt][ng][0] + b0;  v0.y = acc[mt][ng][1] + b1;
            v1.x = acc[mt][ng][2] + b0;  v1.y = acc[mt][ng][3] + b1;
            if (ACT) {
                v0.x = v0.x > 0.f ? v0.x + 1.f : __expf(v0.x);
                v0.y = v0.y > 0.f ? v0.y + 1.f : __expf(v0.y);
                v1.x = v1.x > 0.f ? v1.x + 1.f : __expf(v1.x);
                v1.y = v1.y > 0.f ? v1.y + 1.f : __expf(v1.y);
            }
            *(float2*)&C[(size_t)row0 * NCOL + col]       = v0;
            *(float2*)&C[(size_t)(row0 + 8) * NCOL + col] = v1;
        }
    }
}

// ---------------- fp32 -> fp16 hi/lo split (activations) ----------------
__global__ void __launch_bounds__(256) asplit(const float* __restrict__ x,
                                              __half* __restrict__ hi,
                                              __half* __restrict__ lo, int n4)
{
    int i = blockIdx.x * 256 + threadIdx.x;
    if (i >= n4) return;
    float4 v = ((const float4*)x)[i];
    __half h0 = __float2half(v.x), h1 = __float2half(v.y);
    __half h2 = __float2half(v.z), h3 = __float2half(v.w);
    __half2* H = (__half2*)hi;
    __half2* L = (__half2*)lo;
    H[2*i]   = __halves2half2(h0, h1);
    H[2*i+1] = __halves2half2(h2, h3);
    L[2*i]   = __halves2half2(__float2half(v.x - __half2float(h0)),
                              __float2half(v.y - __half2float(h1)));
    L[2*i+1] = __halves2half2(__float2half(v.z - __half2float(h2)),
                              __float2half(v.w - __half2float(h3)));
}

// ---------------- weight transpose + split: W[K,N] -> Wt_hi/lo[N,K] ---------
__global__ void __launch_bounds__(256) wsplit(const float* __restrict__ W,
                                              __half* __restrict__ thi,
                                              __half* __restrict__ tlo)
{
    __shared__ float tile[32][33];
    const int n0 = blockIdx.x * 32, k0 = blockIdx.y * 32;
    const int tx = threadIdx.x & 31, ty = threadIdx.x >> 5;
#pragma unroll
    for (int r = ty; r < 32; r += 8)
        tile[r][tx] = W[(size_t)(k0 + r) * NCOL + n0 + tx];
    __syncthreads();
#pragma unroll
    for (int r = ty; r < 32; r += 8) {
        float v = tile[tx][r];   // = W[k0+tx][n0+r]
        __half hh = __float2half(v);
        thi[(size_t)(n0 + r) * KDIM + k0 + tx] = hh;
        tlo[(size_t)(n0 + r) * KDIM + k0 + tx] = __float2half(v - __half2float(hh));
    }
}

// ---------------- kv partial: per (bh, split of 512 t-rows) -----------------
__global__ void __launch_bounds__(256) kv_partial(const float* __restrict__ Kq, const float* __restrict__ Vq,
                                                  float* __restrict__ kvp, float* __restrict__ ksp)
{
    const int bh = blockIdx.x, sp = blockIdx.y;
    const int b = bh >> 4, hd = bh & 15;
    __shared__ float Ks[32][64];
    __shared__ float Vs[32][64];
    const int tid = threadIdx.x;
    const int ty = tid >> 4, tx = tid & 15;
    const float* Kb = Kq + ((size_t)b * Tt + sp * 512) * NCOL + hd * DKk;
    const float* Vb = Vq + ((size_t)b * Tt + sp * 512) * NCOL + hd * DVv;

    float acc[4][4];
#pragma unroll
    for (int i = 0; i < 4; i++)
#pragma unroll
        for (int j = 0; j < 4; j++) acc[i][j] = 0.f;
    float ks = 0.f;

    for (int t0 = 0; t0 < 512; t0 += 32) {
#pragma unroll
        for (int p = 0; p < 2; p++) {
            int idx = tid + p * 256;
            int r = idx >> 4, c = (idx & 15) << 2;
            *(float4*)&Ks[r][c] = *(const float4*)&Kb[(size_t)(t0 + r) * NCOL + c];
            *(float4*)&Vs[r][c] = *(const float4*)&Vb[(size_t)(t0 + r) * NCOL + c];
        }
        __syncthreads();
#pragma unroll 8
        for (int t = 0; t < 32; t++) {
            float rv[4], rk[4];
#pragma unroll
            for (int i = 0; i < 4; i++) rv[i] = Vs[t][ty * 4 + i];
#pragma unroll
            for (int j = 0; j < 4; j++) rk[j] = Ks[t][tx * 4 + j];
#pragma unroll
            for (int i = 0; i < 4; i++)
#pragma unroll
                for (int j = 0; j < 4; j++)
                    acc[i][j] += rv[i] * rk[j];
        }
        if (tid < 64) {
#pragma unroll
            for (int t = 0; t < 32; t++) ks += Ks[t][tid];
        }
        __syncthreads();
    }

    float* o = kvp + (size_t)(sp * 64 + bh) * (DVv * DKk);
#pragma unroll
    for (int i = 0; i < 4; i++) {
        float4 v;
        v.x = acc[i][0]; v.y = acc[i][1]; v.z = acc[i][2]; v.w = acc[i][3];
        *(float4*)&o[(ty * 4 + i) * DKk + tx * 4] = v;
    }
    if (tid < 64) ksp[(sp * 64 + bh) * DKk + tid] = ks;
}

__global__ void __launch_bounds__(256) kv_reduce(const float* __restrict__ kvp, const float* __restrict__ ksp,
                                                 float* __restrict__ kv, float* __restrict__ ksum)
{
    const int bh = blockIdx.x, tid = threadIdx.x;
    for (int i = tid; i < DVv * DKk; i += 256) {
        float s = 0.f;
#pragma unroll
        for (int y = 0; y < 8; y++) s += kvp[(size_t)(y * 64 + bh) * (DVv * DKk) + i];
        kv[(size_t)bh * (DVv * DKk) + i] = s;
    }
    if (tid < DKk) {
        float s = 0.f;
#pragma unroll
        for (int y = 0; y < 8; y++) s += ksp[(y * 64 + bh) * DKk + tid];
        ksum[bh * DKk + tid] = s;
    }
}

// ---------------- attn: writes fp16 hi/lo directly (final GEMM input) -------
__global__ void __launch_bounds__(256) attn_tc(
    const float* __restrict__ Qq, const float* __restrict__ kv,
    const float* __restrict__ ksum,
    __half* __restrict__ ahi, __half* __restrict__ alo)
{
    const int bh = blockIdx.x;
    const int b = bh >> 4, hd = bh & 15;
    const int t0 = blockIdx.y * 64;

    __shared__ float Qs[64][68];
    __shared__ float kvs[64][68];
    __shared__ float nrm[64];
    __shared__ float kss[64];

    const int tid = threadIdx.x;
    const float* Qbase = Qq + ((size_t)(b * Tt + t0)) * NCOL + hd * DKk;

#pragma unroll
    for (int p = 0; p < 4; p++) {
        int idx = tid + p * 256;
        int r = idx >> 4, c = (idx & 15) << 2;
        *(float4*)&Qs[r][c] = *(const float4*)&Qbase[(size_t)r * NCOL + c];
    }
    const float* kvb = kv + (size_t)bh * (DVv * DKk);
#pragma unroll
    for (int p = 0; p < 4; p++) {
        int idx = tid + p * 256;
        int r = idx >> 4, c = (idx & 15) << 2;
        *(float4*)&kvs[r][c] = *(const float4*)&kvb[(size_t)r * DKk + c];
    }
    if (tid < 64) kss[tid] = ksum[bh * DKk + tid];
    __syncthreads();

    if (tid < 64) {
        float s = 0.f;
#pragma unroll
        for (int d = 0; d < 64; d++) s += Qs[tid][d] * kss[d];
        nrm[tid] = 1.f / (s + EPSF);
    }
    __syncthreads();

    const int tm = (tid >> 4) << 2;
    const int tn = (tid & 15) << 2;
    float acc[4][4];
#pragma unroll
    for (int i = 0; i < 4; i++)
#pragma unroll
        for (int j = 0; j < 4; j++) acc[i][j] = 0.f;

#pragma unroll 16
    for (int d = 0; d < 64; d++) {
        float rq[4], rk[4];
#pragma unroll
        for (int i = 0; i < 4; i++) rq[i] = Qs[tm + i][d];
#pragma unroll
        for (int j = 0; j < 4; j++) rk[j] = kvs[tn + j][d];
#pragma unroll
        for (int i = 0; i < 4; i++)
#pragma unroll
            for (int j = 0; j < 4; j++)
                acc[i][j] += rq[i] * rk[j];
    }

#pragma unroll
    for (int i = 0; i < 4; i++) {
        float nr = nrm[tm + i];
        size_t base = ((size_t)(b * Tt + t0 + tm + i)) * NCOL + hd * DVv + tn;
        float v0 = acc[i][0] * nr, v1 = acc[i][1] * nr, v2 = acc[i][2] * nr, v3 = acc[i][3] * nr;
        __half a0 = __float2half(v0), a1 = __float2half(v1);
        __half a2 = __float2half(v2), a3 = __float2half(v3);
        ((__half2*)(ahi + base))[0] = __halves2half2(a0, a1);
        ((__half2*)(ahi + base))[1] = __halves2half2(a2, a3);
        ((__half2*)(alo + base))[0] = __halves2half2(
            __float2half(v0 - __half2float(a0)), __float2half(v1 - __half2float(a1)));
        ((__half2*)(alo + base))[1] = __halves2half2(
            __float2half(v2 - __half2float(a2)), __float2half(v3 - __half2float(a3)));
    }
}

// ---------------- host ----------------
#define SMEM_SZ (12*TILE_SM)   // 122880: both variants use this much

extern "C" void kernel_launch(void* const* d_in, const int* in_sizes, int n_in,
                              void* d_out, int out_size)
{
    (void)in_sizes; (void)n_in; (void)out_size;
    const float* query = (const float*)d_in[0];
    const float* key   = (const float*)d_in[1];
    const float* value = (const float*)d_in[2];
    const float* Wq    = (const float*)d_in[3];
    const float* bq    = (const float*)d_in[4];
    const float* Wk    = (const float*)d_in[5];
    const float* bk    = (const float*)d_in[6];
    const float* Wv    = (const float*)d_in[7];
    const float* bv    = (const float*)d_in[8];
    const float* Wo    = (const float*)d_in[9];
    const float* bo    = (const float*)d_in[10];
    float* out = (float*)d_out;

    float *Qp, *Kp, *Vp, *kvpp, *kspp, *kvv, *kss;
    __half *Ahi, *Alo, *WhiP, *WloP;
    cudaGetSymbolAddress((void**)&Qp,   g_Q);
    cudaGetSymbolAddress((void**)&Kp,   g_K);
    cudaGetSymbolAddress((void**)&Vp,   g_V);
    cudaGetSymbolAddress((void**)&Ahi,  g_Ahi);
    cudaGetSymbolAddress((void**)&Alo,  g_Alo);
    cudaGetSymbolAddress((void**)&WhiP, g_Whi);
    cudaGetSymbolAddress((void**)&WloP, g_Wlo);
    cudaGetSymbolAddress((void**)&kvpp, g_kvp);
    cudaGetSymbolAddress((void**)&kspp, g_ksp);
    cudaGetSymbolAddress((void**)&kvv,  g_kv);
    cudaGetSymbolAddress((void**)&kss,  g_ksum);

    cudaFuncSetAttribute(gemm_mma<0,2>, cudaFuncAttributeMaxDynamicSharedMemorySize, SMEM_SZ);
    cudaFuncSetAttribute(gemm_mma<1,2>, cudaFuncAttributeMaxDynamicSharedMemorySize, SMEM_SZ);
    cudaFuncSetAttribute(gemm_mma<0,3>, cudaFuncAttributeMaxDynamicSharedMemorySize, SMEM_SZ);

    const size_t WSZ = (size_t)NCOL * KDIM;

    // weight prep (transpose + hi/lo split)
    dim3 wgrid(NCOL / 32, KDIM / 32);
    wsplit<<<wgrid, 256>>>(Wq, WhiP + 0 * WSZ, WloP + 0 * WSZ);
    wsplit<<<wgrid, 256>>>(Wk, WhiP + 1 * WSZ, WloP + 1 * WSZ);
    wsplit<<<wgrid, 256>>>(Wv, WhiP + 2 * WSZ, WloP + 2 * WSZ);
    wsplit<<<wgrid, 256>>>(Wo, WhiP + 3 * WSZ, WloP + 3 * WSZ);

    const int n4 = Mrows * KDIM / 4;
    dim3 ggrid(NCOL / 128, Mrows / 128);   // (8, 128)

    // QKV projections: 2-pass fp16 split (A exact to 21 bits, W quantized to fp16)
    asplit<<<n4 / 256, 256>>>(query, Ahi, Alo, n4);
    gemm_mma<1,2><<<ggrid, 256, SMEM_SZ>>>(Ahi, Alo, WhiP + 0 * WSZ, WloP + 0 * WSZ, bq, Qp);
    asplit<<<n4 / 256, 256>>>(key, Ahi, Alo, n4);
    gemm_mma<1,2><<<ggrid, 256, SMEM_SZ>>>(Ahi, Alo, WhiP + 1 * WSZ, WloP + 1 * WSZ, bk, Kp);
    asplit<<<n4 / 256, 256>>>(value, Ahi, Alo, n4);
    gemm_mma<0,2><<<ggrid, 256, SMEM_SZ>>>(Ahi, Alo, WhiP + 2 * WSZ, WloP + 2 * WSZ, bv, Vp);

    kv_partial<<<dim3(64, 8), 256>>>(Kp, Vp, kvpp, kspp);
    kv_reduce<<<64, 256>>>(kvpp, kspp, kvv, kss);
    attn_tc<<<dim3(64, Tt / 64), 256>>>(Qp, kvv, kss, Ahi, Alo);

    // Output GEMM: 3-pass (error lands directly in output; keep near-exact)
    gemm_mma<0,3><<<ggrid, 256, SMEM_SZ>>>(Ahi, Alo, WhiP + 3 * WSZ, WloP + 3 * WSZ, bo, out);
}

// round 5
// speedup vs baseline: 3.5772x; 1.5223x over previous
#include <cuda_runtime.h>
#include <cuda_fp16.h>
#include <cstdint>
#include <cstddef>

#define Bb 4
#define Tt 4096
#define Hh 16
#define DKk 64
#define DVv 64
#define Mrows (Bb*Tt)          // 16384
#define NCOL 1024
#define KDIM 1024
#define EPSF 1e-6f
#define KVSPLIT 16

// ---------------- static scratch ----------------
__device__ float g_Q[(size_t)Mrows*NCOL];
__device__ float g_K[(size_t)Mrows*NCOL];
__device__ float g_V[(size_t)Mrows*NCOL];
__device__ __half g_Ahi[(size_t)Mrows*KDIM];
__device__ __half g_Alo[(size_t)Mrows*KDIM];
__device__ __half g_Whi[4][(size_t)NCOL*KDIM];   // transposed [N,K], fp16
__device__ float g_kvp[KVSPLIT*64*DVv*DKk];
__device__ float g_ksp[KVSPLIT*64*DKk];
__device__ float g_kv[64*DVv*DKk];
__device__ float g_ksum[64*DKk];

// ---------------- PTX helpers (baseline ISA: sm_80 features only) -----------
__device__ __forceinline__ uint32_t s2u(const void* p){
    uint32_t a;
    asm("{ .reg .u64 t; cvta.to.shared.u64 t, %1; cvt.u32.u64 %0, t; }" : "=r"(a) : "l"(p));
    return a;
}
__device__ __forceinline__ void cpa16(uint32_t dst, const void* src){
    asm volatile("cp.async.cg.shared.global [%0], [%1], 16;" :: "r"(dst), "l"(src) : "memory");
}
__device__ __forceinline__ void cp_commit(){
    asm volatile("cp.async.commit_group;" ::: "memory");
}
template<int N>
__device__ __forceinline__ void cp_waitg(){
    asm volatile("cp.async.wait_group %0;" :: "n"(N) : "memory");
}
__device__ __forceinline__ void ldm4(uint32_t* r, uint32_t addr){
    asm volatile("ldmatrix.sync.aligned.m8n8.x4.shared.b16 {%0,%1,%2,%3}, [%4];"
        : "=r"(r[0]), "=r"(r[1]), "=r"(r[2]), "=r"(r[3]) : "r"(addr));
}
__device__ __forceinline__ void mma16816(float* c, const uint32_t* a, uint32_t b0, uint32_t b1){
    asm volatile("mma.sync.aligned.m16n8k16.row.col.f32.f16.f16.f32 "
        "{%0,%1,%2,%3}, {%4,%5,%6,%7}, {%8,%9}, {%0,%1,%2,%3};"
        : "+f"(c[0]), "+f"(c[1]), "+f"(c[2]), "+f"(c[3])
        : "r"(a[0]), "r"(a[1]), "r"(a[2]), "r"(a[3]), "r"(b0), "r"(b1));
}

// ---------------- HMMA GEMM: C = act(A[M,K] @ W[N,K]^T + bias) --------------
// Tile 128x128, k-chunk 32, cp.async pipeline, fp16.
// NPASS=1: C = Ahi*Bhi                (2 smem tiles/stage, 5 stages)
// NPASS=2: C = (Ahi+Alo)*Bhi          (3 smem tiles/stage, 4 stages)
#define RSTRIDE 80                 // bytes per 32-half row (16B pad: conflict-free ldmatrix)
#define TILE_SM (128*RSTRIDE)      // 10240 bytes per [128][32] tile
#define NKCH (KDIM/32)             // 32 k-chunks

template<int ACT, int NPASS>
__global__ void __launch_bounds__(256, 1) gemm_mma(
    const __half* __restrict__ Ahi, const __half* __restrict__ Alo,
    const __half* __restrict__ Whi,
    const float* __restrict__ bias, float* __restrict__ C)
{
    constexpr int NTILE = NPASS + 1;             // A tiles + B tile
    constexpr int STGB  = NTILE * TILE_SM;
    constexpr int NSTG  = (NPASS == 1) ? 5 : 4;
    constexpr uint32_t BOFF = NPASS * TILE_SM;   // B tile offset within stage

    extern __shared__ __align__(128) char smem[];
    const uint32_t sb = s2u(smem);
    const int tid  = threadIdx.x;
    const int warp = tid >> 5, lane = tid & 31;
    const int wm = warp & 3, wn = warp >> 2;       // warp tile: 32(m) x 64(n)
    const int bm = blockIdx.y * 128, bn = blockIdx.x * 128;

    // loader coords: each thread brings 2x16B (32B contiguous) per tile
    const int lrow = tid >> 1;          // 0..127
    const int lc   = (tid & 1) * 2;     // chunk 0 or 2

    const __half* gA0 = Ahi + (size_t)(bm + lrow) * KDIM + lc * 8;
    const __half* gA1 = Alo + (size_t)(bm + lrow) * KDIM + lc * 8;
    const __half* gB0 = Whi + (size_t)(bn + lrow) * KDIM + lc * 8;
    const uint32_t dofs = lrow * RSTRIDE + lc * 16;

    float acc[2][8][4];
#pragma unroll
    for (int i = 0; i < 2; i++)
#pragma unroll
        for (int j = 0; j < 8; j++)
#pragma unroll
            for (int q = 0; q < 4; q++) acc[i][j][q] = 0.f;

#define ISSUE(kt, s) do {                                   \
        uint32_t st_ = sb + (s) * STGB + dofs;              \
        int ko_ = (kt) * 32;                                \
        cpa16(st_,                  gA0 + ko_);             \
        cpa16(st_ + 16,             gA0 + ko_ + 8);         \
        if (NPASS == 2) {                                   \
            cpa16(st_ +   TILE_SM,      gA1 + ko_);         \
            cpa16(st_ +   TILE_SM + 16, gA1 + ko_ + 8);     \
        }                                                   \
        cpa16(st_ + BOFF,           gB0 + ko_);             \
        cpa16(st_ + BOFF + 16,      gB0 + ko_ + 8);         \
    } while (0)

#pragma unroll
    for (int s = 0; s < NSTG - 1; s++) { ISSUE(s, s); cp_commit(); }

    const int lm = lane & 15, lh = lane >> 4;

    for (int kt = 0; kt < NKCH; kt++) {
        cp_waitg<NSTG - 2>();
        __syncthreads();
        if (kt + NSTG - 1 < NKCH) ISSUE(kt + NSTG - 1, (kt + NSTG - 1) % NSTG);
        cp_commit();

        const uint32_t st = sb + (kt % NSTG) * STGB;
#pragma unroll
        for (int kk = 0; kk < 2; kk++) {
            const uint32_t kcol = kk * 32 + lh * 16;
            uint32_t ah[2][4], al[2][4], bh[4][4];
#pragma unroll
            for (int mt = 0; mt < 2; mt++) {
                uint32_t r = (uint32_t)(wm * 32 + mt * 16 + lm);
                ldm4(ah[mt], st + r * RSTRIDE + kcol);
                if (NPASS == 2)
                    ldm4(al[mt], st + TILE_SM + r * RSTRIDE + kcol);
            }
#pragma unroll
            for (int g = 0; g < 4; g++) {
                uint32_t r = (uint32_t)(wn * 64 + g * 16 + lm);
                ldm4(bh[g], st + BOFF + r * RSTRIDE + kcol);
            }
            // pass 1: Ahi * Bhi
#pragma unroll
            for (int mt = 0; mt < 2; mt++)
#pragma unroll
                for (int g = 0; g < 4; g++) {
                    mma16816(acc[mt][2*g],   ah[mt], bh[g][0], bh[g][2]);
                    mma16816(acc[mt][2*g+1], ah[mt], bh[g][1], bh[g][3]);
                }
            // pass 2: Alo * Bhi
            if (NPASS == 2) {
#pragma unroll
                for (int mt = 0; mt < 2; mt++)
#pragma unroll
                    for (int g = 0; g < 4; g++) {
                        mma16816(acc[mt][2*g],   al[mt], bh[g][0], bh[g][2]);
                        mma16816(acc[mt][2*g+1], al[mt], bh[g][1], bh[g][3]);
                    }
            }
        }
    }
#undef ISSUE

    // epilogue: direct stores with bias (+ optional ELU+1)
#pragma unroll
    for (int mt = 0; mt < 2; mt++) {
        const int row0 = bm + wm * 32 + mt * 16 + (lane >> 2);
#pragma unroll
        for (int ng = 0; ng < 8; ng++) {
            const int col = bn + wn * 64 + ng * 8 + 2 * (lane & 3);
            const float b0 = bias[col], b1 = bias[col + 1];
            float2 v0, v1;
            v0.x = acc[mt][ng][0] + b0;  v0.y = acc[mt][ng][1] + b1;
            v1.x = acc[mt][ng][2] + b0;  v1.y = acc[mt][ng][3] + b1;
            if (ACT) {
                v0.x = v0.x > 0.f ? v0.x + 1.f : __expf(v0.x);
                v0.y = v0.y > 0.f ? v0.y + 1.f : __expf(v0.y);
                v1.x = v1.x > 0.f ? v1.x + 1.f : __expf(v1.x);
                v1.y = v1.y > 0.f ? v1.y + 1.f : __expf(v1.y);
            }
            *(float2*)&C[(size_t)row0 * NCOL + col]       = v0;
            *(float2*)&C[(size_t)(row0 + 8) * NCOL + col] = v1;
        }
    }
}

// ---------------- fp32 -> fp16 (hi only) ----------------
__global__ void __launch_bounds__(256) asplit_hi(const float* __restrict__ x,
                                                 __half* __restrict__ hi, int n4)
{
    int i = blockIdx.x * 256 + threadIdx.x;
    if (i >= n4) return;
    float4 v = ((const float4*)x)[i];
    __half2* H = (__half2*)hi;
    H[2*i]   = __halves2half2(__float2half(v.x), __float2half(v.y));
    H[2*i+1] = __halves2half2(__float2half(v.z), __float2half(v.w));
}

// ---------------- weight transpose + fp16: W[K,N] -> Wt_hi[N,K] ---------
__global__ void __launch_bounds__(256) wsplit(const float* __restrict__ W,
                                              __half* __restrict__ thi)
{
    __shared__ float tile[32][33];
    const int n0 = blockIdx.x * 32, k0 = blockIdx.y * 32;
    const int tx = threadIdx.x & 31, ty = threadIdx.x >> 5;
#pragma unroll
    for (int r = ty; r < 32; r += 8)
        tile[r][tx] = W[(size_t)(k0 + r) * NCOL + n0 + tx];
    __syncthreads();
#pragma unroll
    for (int r = ty; r < 32; r += 8)
        thi[(size_t)(n0 + r) * KDIM + k0 + tx] = __float2half(tile[tx][r]);
}

// ---------------- kv partial: per (bh, split of Tt/KVSPLIT t-rows) ----------
__global__ void __launch_bounds__(256) kv_partial(const float* __restrict__ Kq, const float* __restrict__ Vq,
                                                  float* __restrict__ kvp, float* __restrict__ ksp)
{
    const int bh = blockIdx.x, sp = blockIdx.y;
    const int b = bh >> 4, hd = bh & 15;
    const int TSEG = Tt / KVSPLIT;          // 256
    __shared__ float Ks[32][64];
    __shared__ float Vs[32][64];
    const int tid = threadIdx.x;
    const int ty = tid >> 4, tx = tid & 15;
    const float* Kb = Kq + ((size_t)b * Tt + sp * TSEG) * NCOL + hd * DKk;
    const float* Vb = Vq + ((size_t)b * Tt + sp * TSEG) * NCOL + hd * DVv;

    float acc[4][4];
#pragma unroll
    for (int i = 0; i < 4; i++)
#pragma unroll
        for (int j = 0; j < 4; j++) acc[i][j] = 0.f;
    float ks = 0.f;

    for (int t0 = 0; t0 < TSEG; t0 += 32) {
#pragma unroll
        for (int p = 0; p < 2; p++) {
            int idx = tid + p * 256;
            int r = idx >> 4, c = (idx & 15) << 2;
            *(float4*)&Ks[r][c] = *(const float4*)&Kb[(size_t)(t0 + r) * NCOL + c];
            *(float4*)&Vs[r][c] = *(const float4*)&Vb[(size_t)(t0 + r) * NCOL + c];
        }
        __syncthreads();
#pragma unroll 8
        for (int t = 0; t < 32; t++) {
            float rv[4], rk[4];
#pragma unroll
            for (int i = 0; i < 4; i++) rv[i] = Vs[t][ty * 4 + i];
#pragma unroll
            for (int j = 0; j < 4; j++) rk[j] = Ks[t][tx * 4 + j];
#pragma unroll
            for (int i = 0; i < 4; i++)
#pragma unroll
                for (int j = 0; j < 4; j++)
                    acc[i][j] += rv[i] * rk[j];
        }
        if (tid < 64) {
#pragma unroll
            for (int t = 0; t < 32; t++) ks += Ks[t][tid];
        }
        __syncthreads();
    }

    float* o = kvp + (size_t)(sp * 64 + bh) * (DVv * DKk);
#pragma unroll
    for (int i = 0; i < 4; i++) {
        float4 v;
        v.x = acc[i][0]; v.y = acc[i][1]; v.z = acc[i][2]; v.w = acc[i][3];
        *(float4*)&o[(ty * 4 + i) * DKk + tx * 4] = v;
    }
    if (tid < 64) ksp[(sp * 64 + bh) * DKk + tid] = ks;
}

__global__ void __launch_bounds__(256) kv_reduce(const float* __restrict__ kvp, const float* __restrict__ ksp,
                                                 float* __restrict__ kv, float* __restrict__ ksum)
{
    const int bh = blockIdx.x, tid = threadIdx.x;
    for (int i = tid; i < DVv * DKk; i += 256) {
        float s = 0.f;
#pragma unroll
        for (int y = 0; y < KVSPLIT; y++) s += kvp[(size_t)(y * 64 + bh) * (DVv * DKk) + i];
        kv[(size_t)bh * (DVv * DKk) + i] = s;
    }
    if (tid < DKk) {
        float s = 0.f;
#pragma unroll
        for (int y = 0; y < KVSPLIT; y++) s += ksp[(y * 64 + bh) * DKk + tid];
        ksum[bh * DKk + tid] = s;
    }
}

// ---------------- attn: writes fp16 hi/lo directly (final GEMM input) -------
__global__ void __launch_bounds__(256) attn_tc(
    const float* __restrict__ Qq, const float* __restrict__ kv,
    const float* __restrict__ ksum,
    __half* __restrict__ ahi, __half* __restrict__ alo)
{
    const int bh = blockIdx.x;
    const int b = bh >> 4, hd = bh & 15;
    const int t0 = blockIdx.y * 64;

    __shared__ float Qs[64][68];
    __shared__ float kvs[64][68];
    __shared__ float nrm[64];
    __shared__ float kss[64];

    const int tid = threadIdx.x;
    const float* Qbase = Qq + ((size_t)(b * Tt + t0)) * NCOL + hd * DKk;

#pragma unroll
    for (int p = 0; p < 4; p++) {
        int idx = tid + p * 256;
        int r = idx >> 4, c = (idx & 15) << 2;
        *(float4*)&Qs[r][c] = *(const float4*)&Qbase[(size_t)r * NCOL + c];
    }
    const float* kvb = kv + (size_t)bh * (DVv * DKk);
#pragma unroll
    for (int p = 0; p < 4; p++) {
        int idx = tid + p * 256;
        int r = idx >> 4, c = (idx & 15) << 2;
        *(float4*)&kvs[r][c] = *(const float4*)&kvb[(size_t)r * DKk + c];
    }
    if (tid < 64) kss[tid] = ksum[bh * DKk + tid];
    __syncthreads();

    if (tid < 64) {
        float s = 0.f;
#pragma unroll
        for (int d = 0; d < 64; d++) s += Qs[tid][d] * kss[d];
        nrm[tid] = 1.f / (s + EPSF);
    }
    __syncthreads();

    const int tm = (tid >> 4) << 2;
    const int tn = (tid & 15) << 2;
    float acc[4][4];
#pragma unroll
    for (int i = 0; i < 4; i++)
#pragma unroll
        for (int j = 0; j < 4; j++) acc[i][j] = 0.f;

#pragma unroll 16
    for (int d = 0; d < 64; d++) {
        float rq[4], rk[4];
#pragma unroll
        for (int i = 0; i < 4; i++) rq[i] = Qs[tm + i][d];
#pragma unroll
        for (int j = 0; j < 4; j++) rk[j] = kvs[tn + j][d];
#pragma unroll
        for (int i = 0; i < 4; i++)
#pragma unroll
            for (int j = 0; j < 4; j++)
                acc[i][j] += rq[i] * rk[j];
    }

#pragma unroll
    for (int i = 0; i < 4; i++) {
        float nr = nrm[tm + i];
        size_t base = ((size_t)(b * Tt + t0 + tm + i)) * NCOL + hd * DVv + tn;
        float v0 = acc[i][0] * nr, v1 = acc[i][1] * nr, v2 = acc[i][2] * nr, v3 = acc[i][3] * nr;
        __half a0 = __float2half(v0), a1 = __float2half(v1);
        __half a2 = __float2half(v2), a3 = __float2half(v3);
        ((__half2*)(ahi + base))[0] = __halves2half2(a0, a1);
        ((__half2*)(ahi + base))[1] = __halves2half2(a2, a3);
        ((__half2*)(alo + base))[0] = __halves2half2(
            __float2half(v0 - __half2float(a0)), __float2half(v1 - __half2float(a1)));
        ((__half2*)(alo + base))[1] = __halves2half2(
            __float2half(v2 - __half2float(a2)), __float2half(v3 - __half2float(a3)));
    }
}

// ---------------- host ----------------
#define SMEM_P1 (5*2*TILE_SM)   // 102400
#define SMEM_P2 (4*3*TILE_SM)   // 122880

extern "C" void kernel_launch(void* const* d_in, const int* in_sizes, int n_in,
                              void* d_out, int out_size)
{
    (void)in_sizes; (void)n_in; (void)out_size;
    const float* query = (const float*)d_in[0];
    const float* key   = (const float*)d_in[1];
    const float* value = (const float*)d_in[2];
    const float* Wq    = (const float*)d_in[3];
    const float* bq    = (const float*)d_in[4];
    const float* Wk    = (const float*)d_in[5];
    const float* bk    = (const float*)d_in[6];
    const float* Wv    = (const float*)d_in[7];
    const float* bv    = (const float*)d_in[8];
    const float* Wo    = (const float*)d_in[9];
    const float* bo    = (const float*)d_in[10];
    float* out = (float*)d_out;

    float *Qp, *Kp, *Vp, *kvpp, *kspp, *kvv, *kss;
    __half *Ahi, *Alo, *WhiP;
    cudaGetSymbolAddress((void**)&Qp,   g_Q);
    cudaGetSymbolAddress((void**)&Kp,   g_K);
    cudaGetSymbolAddress((void**)&Vp,   g_V);
    cudaGetSymbolAddress((void**)&Ahi,  g_Ahi);
    cudaGetSymbolAddress((void**)&Alo,  g_Alo);
    cudaGetSymbolAddress((void**)&WhiP, g_Whi);
    cudaGetSymbolAddress((void**)&kvpp, g_kvp);
    cudaGetSymbolAddress((void**)&kspp, g_ksp);
    cudaGetSymbolAddress((void**)&kvv,  g_kv);
    cudaGetSymbolAddress((void**)&kss,  g_ksum);

    cudaFuncSetAttribute(gemm_mma<1,1>, cudaFuncAttributeMaxDynamicSharedMemorySize, SMEM_P1);
    cudaFuncSetAttribute(gemm_mma<0,1>, cudaFuncAttributeMaxDynamicSharedMemorySize, SMEM_P1);
    cudaFuncSetAttribute(gemm_mma<0,2>, cudaFuncAttributeMaxDynamicSharedMemorySize, SMEM_P2);

    const size_t WSZ = (size_t)NCOL * KDIM;

    // weight prep (transpose + fp16)
    dim3 wgrid(NCOL / 32, KDIM / 32);
    wsplit<<<wgrid, 256>>>(Wq, WhiP + 0 * WSZ);
    wsplit<<<wgrid, 256>>>(Wk, WhiP + 1 * WSZ);
    wsplit<<<wgrid, 256>>>(Wv, WhiP + 2 * WSZ);
    wsplit<<<wgrid, 256>>>(Wo, WhiP + 3 * WSZ);

    const int n4 = Mrows * KDIM / 4;
    dim3 ggrid(NCOL / 128, Mrows / 128);   // (8, 128)

    // QKV projections: 1-pass fp16
    asplit_hi<<<n4 / 256, 256>>>(query, Ahi, n4);
    gemm_mma<1,1><<<ggrid, 256, SMEM_P1>>>(Ahi, Alo, WhiP + 0 * WSZ, bq, Qp);
    asplit_hi<<<n4 / 256, 256>>>(key, Ahi, n4);
    gemm_mma<1,1><<<ggrid, 256, SMEM_P1>>>(Ahi, Alo, WhiP + 1 * WSZ, bk, Kp);
    asplit_hi<<<n4 / 256, 256>>>(value, Ahi, n4);
    gemm_mma<0,1><<<ggrid, 256, SMEM_P1>>>(Ahi, Alo, WhiP + 2 * WSZ, bv, Vp);

    kv_partial<<<dim3(64, KVSPLIT), 256>>>(Kp, Vp, kvpp, kspp);
    kv_reduce<<<64, 256>>>(kvpp, kspp, kvv, kss);
    attn_tc<<<dim3(64, Tt / 64), 256>>>(Qp, kvv, kss, Ahi, Alo);

    // Output GEMM: 2-pass ((Ahi+Alo)*Bhi) — attn output kept near-exact
    gemm_mma<0,2><<<ggrid, 256, SMEM_P2>>>(Ahi, Alo, WhiP + 3 * WSZ, bo, out);
}

// round 6
// speedup vs baseline: 4.1220x; 1.1523x over previous
#include <cuda_runtime.h>
#include <cuda_fp16.h>
#include <cstdint>
#include <cstddef>

#define Bb 4
#define Tt 4096
#define Hh 16
#define DKk 64
#define DVv 64
#define Mrows (Bb*Tt)          // 16384
#define NCOL 1024
#define KDIM 1024
#define EPSF 1e-6f
#define KVSPLIT 16

// ---------------- static scratch ----------------
__device__ __half g_Xin[3][(size_t)Mrows*KDIM];   // fp16 inputs (q,k,v source)
__device__ __half g_Qh[(size_t)Mrows*NCOL];       // fp16 projected Q (phi applied)
__device__ __half g_Kh[(size_t)Mrows*NCOL];
__device__ __half g_Vh[(size_t)Mrows*NCOL];
__device__ __half g_At[(size_t)Mrows*NCOL];       // fp16 attn output (final GEMM input)
__device__ __half g_Whi[4][(size_t)NCOL*KDIM];    // transposed [N,K], fp16
__device__ float g_kvp[KVSPLIT*64*DVv*DKk];
__device__ float g_ksp[KVSPLIT*64*DKk];
__device__ float g_kv[64*DVv*DKk];
__device__ float g_ksum[64*DKk];

// ---------------- PTX helpers (baseline ISA: sm_80 features only) -----------
__device__ __forceinline__ uint32_t s2u(const void* p){
    uint32_t a;
    asm("{ .reg .u64 t; cvta.to.shared.u64 t, %1; cvt.u32.u64 %0, t; }" : "=r"(a) : "l"(p));
    return a;
}
__device__ __forceinline__ void cpa16(uint32_t dst, const void* src){
    asm volatile("cp.async.cg.shared.global [%0], [%1], 16;" :: "r"(dst), "l"(src) : "memory");
}
__device__ __forceinline__ void cp_commit(){
    asm volatile("cp.async.commit_group;" ::: "memory");
}
template<int N>
__device__ __forceinline__ void cp_waitg(){
    asm volatile("cp.async.wait_group %0;" :: "n"(N) : "memory");
}
__device__ __forceinline__ void ldm4(uint32_t* r, uint32_t addr){
    asm volatile("ldmatrix.sync.aligned.m8n8.x4.shared.b16 {%0,%1,%2,%3}, [%4];"
        : "=r"(r[0]), "=r"(r[1]), "=r"(r[2]), "=r"(r[3]) : "r"(addr));
}
__device__ __forceinline__ void mma16816(float* c, const uint32_t* a, uint32_t b0, uint32_t b1){
    asm volatile("mma.sync.aligned.m16n8k16.row.col.f32.f16.f16.f32 "
        "{%0,%1,%2,%3}, {%4,%5,%6,%7}, {%8,%9}, {%0,%1,%2,%3};"
        : "+f"(c[0]), "+f"(c[1]), "+f"(c[2]), "+f"(c[3])
        : "r"(a[0]), "r"(a[1]), "r"(a[2]), "r"(a[3]), "r"(b0), "r"(b1));
}

// ---------------- HMMA GEMM (1-pass): C = act(A @ W^T + bias) ---------------
// Tile 128x128, k-chunk 32, 5-stage cp.async pipeline.
// OUT16=1 -> writes __half C, OUT16=0 -> writes float C.
#define RSTRIDE 80                 // bytes per 32-half row (16B pad: conflict-free ldmatrix)
#define TILE_SM (128*RSTRIDE)      // 10240 bytes per [128][32] tile
#define NKCH (KDIM/32)             // 32 k-chunks
#define NSTG 5
#define STGB (2*TILE_SM)
#define SMEM_G (NSTG*STGB)         // 102400

template<int ACT, int OUT16>
__global__ void __launch_bounds__(256, 1) gemm_mma(
    const __half* __restrict__ A, const __half* __restrict__ W,
    const float* __restrict__ bias, void* __restrict__ Cv)
{
    extern __shared__ __align__(128) char smem[];
    const uint32_t sb = s2u(smem);
    const int tid  = threadIdx.x;
    const int warp = tid >> 5, lane = tid & 31;
    const int wm = warp & 3, wn = warp >> 2;       // warp tile: 32(m) x 64(n)
    const int bm = blockIdx.y * 128, bn = blockIdx.x * 128;

    const int lrow = tid >> 1;          // 0..127
    const int lc   = (tid & 1) * 2;     // chunk 0 or 2

    const __half* gA = A + (size_t)(bm + lrow) * KDIM + lc * 8;
    const __half* gB = W + (size_t)(bn + lrow) * KDIM + lc * 8;
    const uint32_t dofs = lrow * RSTRIDE + lc * 16;

    float acc[2][8][4];
#pragma unroll
    for (int i = 0; i < 2; i++)
#pragma unroll
        for (int j = 0; j < 8; j++)
#pragma unroll
            for (int q = 0; q < 4; q++) acc[i][j][q] = 0.f;

#define ISSUE(kt, s) do {                                   \
        uint32_t st_ = sb + (s) * STGB + dofs;              \
        int ko_ = (kt) * 32;                                \
        cpa16(st_,                gA + ko_);                \
        cpa16(st_ + 16,           gA + ko_ + 8);            \
        cpa16(st_ + TILE_SM,      gB + ko_);                \
        cpa16(st_ + TILE_SM + 16, gB + ko_ + 8);            \
    } while (0)

#pragma unroll
    for (int s = 0; s < NSTG - 1; s++) { ISSUE(s, s); cp_commit(); }

    const int lm = lane & 15, lh = lane >> 4;

    for (int kt = 0; kt < NKCH; kt++) {
        cp_waitg<NSTG - 2>();
        __syncthreads();
        if (kt + NSTG - 1 < NKCH) ISSUE(kt + NSTG - 1, (kt + NSTG - 1) % NSTG);
        cp_commit();

        const uint32_t st = sb + (kt % NSTG) * STGB;
#pragma unroll
        for (int kk = 0; kk < 2; kk++) {
            const uint32_t kcol = kk * 32 + lh * 16;
            uint32_t ah[2][4], bh[4][4];
#pragma unroll
            for (int mt = 0; mt < 2; mt++) {
                uint32_t r = (uint32_t)(wm * 32 + mt * 16 + lm);
                ldm4(ah[mt], st + r * RSTRIDE + kcol);
            }
#pragma unroll
            for (int g = 0; g < 4; g++) {
                uint32_t r = (uint32_t)(wn * 64 + g * 16 + lm);
                ldm4(bh[g], st + TILE_SM + r * RSTRIDE + kcol);
            }
#pragma unroll
            for (int mt = 0; mt < 2; mt++)
#pragma unroll
                for (int g = 0; g < 4; g++) {
                    mma16816(acc[mt][2*g],   ah[mt], bh[g][0], bh[g][2]);
                    mma16816(acc[mt][2*g+1], ah[mt], bh[g][1], bh[g][3]);
                }
        }
    }
#undef ISSUE

    // epilogue: bias (+ELU+1), write fp16 or fp32
#pragma unroll
    for (int mt = 0; mt < 2; mt++) {
        const int row0 = bm + wm * 32 + mt * 16 + (lane >> 2);
#pragma unroll
        for (int ng = 0; ng < 8; ng++) {
            const int col = bn + wn * 64 + ng * 8 + 2 * (lane & 3);
            const float b0 = bias[col], b1 = bias[col + 1];
            float2 v0, v1;
            v0.x = acc[mt][ng][0] + b0;  v0.y = acc[mt][ng][1] + b1;
            v1.x = acc[mt][ng][2] + b0;  v1.y = acc[mt][ng][3] + b1;
            if (ACT) {
                v0.x = v0.x > 0.f ? v0.x + 1.f : __expf(v0.x);
                v0.y = v0.y > 0.f ? v0.y + 1.f : __expf(v0.y);
                v1.x = v1.x > 0.f ? v1.x + 1.f : __expf(v1.x);
                v1.y = v1.y > 0.f ? v1.y + 1.f : __expf(v1.y);
            }
            if (OUT16) {
                __half* C = (__half*)Cv;
                *(__half2*)&C[(size_t)row0 * NCOL + col] =
                    __halves2half2(__float2half(v0.x), __float2half(v0.y));
                *(__half2*)&C[(size_t)(row0 + 8) * NCOL + col] =
                    __halves2half2(__float2half(v1.x), __float2half(v1.y));
            } else {
                float* C = (float*)Cv;
                *(float2*)&C[(size_t)row0 * NCOL + col]       = v0;
                *(float2*)&C[(size_t)(row0 + 8) * NCOL + col] = v1;
            }
        }
    }
}

// ---------------- fp32 -> fp16 for q,k,v inputs (one launch) ----------------
__global__ void __launch_bounds__(256) aconv3(const float* __restrict__ q,
                                              const float* __restrict__ k,
                                              const float* __restrict__ v,
                                              __half* __restrict__ dst, int n4)
{
    const float* src = (blockIdx.y == 0) ? q : (blockIdx.y == 1) ? k : v;
    __half* d = dst + (size_t)blockIdx.y * Mrows * KDIM;
    int i = blockIdx.x * 256 + threadIdx.x;
    if (i >= n4) return;
    float4 val = ((const float4*)src)[i];
    __half2* H = (__half2*)d;
    H[2*i]   = __halves2half2(__float2half(val.x), __float2half(val.y));
    H[2*i+1] = __halves2half2(__float2half(val.z), __float2half(val.w));
}

// ---------------- weight transpose + fp16: W[K,N] -> Wt[N,K] (one launch) ---
__global__ void __launch_bounds__(256) wsplit4(const float* __restrict__ W0,
                                               const float* __restrict__ W1,
                                               const float* __restrict__ W2,
                                               const float* __restrict__ W3,
                                               __half* __restrict__ dst)
{
    const int wsel = blockIdx.z;
    const float* W = (wsel == 0) ? W0 : (wsel == 1) ? W1 : (wsel == 2) ? W2 : W3;
    __half* thi = dst + (size_t)wsel * NCOL * KDIM;

    __shared__ float tile[32][33];
    const int n0 = blockIdx.x * 32, k0 = blockIdx.y * 32;
    const int tx = threadIdx.x & 31, ty = threadIdx.x >> 5;
#pragma unroll
    for (int r = ty; r < 32; r += 8)
        tile[r][tx] = W[(size_t)(k0 + r) * NCOL + n0 + tx];
    __syncthreads();
#pragma unroll
    for (int r = ty; r < 32; r += 8)
        thi[(size_t)(n0 + r) * KDIM + k0 + tx] = __float2half(tile[tx][r]);
}

// ---------------- kv partial over fp16 K,V ----------------------------------
__global__ void __launch_bounds__(256) kv_partial(const __half* __restrict__ Kq,
                                                  const __half* __restrict__ Vq,
                                                  float* __restrict__ kvp, float* __restrict__ ksp)
{
    const int bh = blockIdx.x, sp = blockIdx.y;
    const int b = bh >> 4, hd = bh & 15;
    const int TSEG = Tt / KVSPLIT;          // 256
    __shared__ float Ks[32][64];
    __shared__ float Vs[32][64];
    const int tid = threadIdx.x;
    const int ty = tid >> 4, tx = tid & 15;
    const __half* Kb = Kq + ((size_t)b * Tt + sp * TSEG) * NCOL + hd * DKk;
    const __half* Vb = Vq + ((size_t)b * Tt + sp * TSEG) * NCOL + hd * DVv;

    const int lr = tid >> 3;            // 0..31
    const int lcc = (tid & 7) * 8;      // 0..56

    float acc[4][4];
#pragma unroll
    for (int i = 0; i < 4; i++)
#pragma unroll
        for (int j = 0; j < 4; j++) acc[i][j] = 0.f;
    float ks = 0.f;

    for (int t0 = 0; t0 < TSEG; t0 += 32) {
        {
            uint4 kraw = *(const uint4*)&Kb[(size_t)(t0 + lr) * NCOL + lcc];
            uint4 vraw = *(const uint4*)&Vb[(size_t)(t0 + lr) * NCOL + lcc];
            const __half2* kh = (const __half2*)&kraw;
            const __half2* vh = (const __half2*)&vraw;
#pragma unroll
            for (int j = 0; j < 4; j++) {
                float2 kf = __half22float2(kh[j]);
                float2 vf = __half22float2(vh[j]);
                Ks[lr][lcc + 2*j]     = kf.x;
                Ks[lr][lcc + 2*j + 1] = kf.y;
                Vs[lr][lcc + 2*j]     = vf.x;
                Vs[lr][lcc + 2*j + 1] = vf.y;
            }
        }
        __syncthreads();
#pragma unroll 8
        for (int t = 0; t < 32; t++) {
            float rv[4], rk[4];
#pragma unroll
            for (int i = 0; i < 4; i++) rv[i] = Vs[t][ty * 4 + i];
#pragma unroll
            for (int j = 0; j < 4; j++) rk[j] = Ks[t][tx * 4 + j];
#pragma unroll
            for (int i = 0; i < 4; i++)
#pragma unroll
                for (int j = 0; j < 4; j++)
                    acc[i][j] += rv[i] * rk[j];
        }
        if (tid < 64) {
#pragma unroll
            for (int t = 0; t < 32; t++) ks += Ks[t][tid];
        }
        __syncthreads();
    }

    float* o = kvp + (size_t)(sp * 64 + bh) * (DVv * DKk);
#pragma unroll
    for (int i = 0; i < 4; i++) {
        float4 v;
        v.x = acc[i][0]; v.y = acc[i][1]; v.z = acc[i][2]; v.w = acc[i][3];
        *(float4*)&o[(ty * 4 + i) * DKk + tx * 4] = v;
    }
    if (tid < 64) ksp[(sp * 64 + bh) * DKk + tid] = ks;
}

__global__ void __launch_bounds__(256) kv_reduce(const float* __restrict__ kvp, const float* __restrict__ ksp,
                                                 float* __restrict__ kv, float* __restrict__ ksum)
{
    const int bh = blockIdx.x, tid = threadIdx.x;
    for (int i = tid; i < DVv * DKk; i += 256) {
        float s = 0.f;
#pragma unroll
        for (int y = 0; y < KVSPLIT; y++) s += kvp[(size_t)(y * 64 + bh) * (DVv * DKk) + i];
        kv[(size_t)bh * (DVv * DKk) + i] = s;
    }
    if (tid < DKk) {
        float s = 0.f;
#pragma unroll
        for (int y = 0; y < KVSPLIT; y++) s += ksp[(y * 64 + bh) * DKk + tid];
        ksum[bh * DKk + tid] = s;
    }
}

// ---------------- attn: fp16 Q in, fp16 out ---------------------------------
__global__ void __launch_bounds__(256) attn_tc(
    const __half* __restrict__ Qq, const float* __restrict__ kv,
    const float* __restrict__ ksum, __half* __restrict__ aout)
{
    const int bh = blockIdx.x;
    const int b = bh >> 4, hd = bh & 15;
    const int t0 = blockIdx.y * 64;

    __shared__ float Qs[64][68];
    __shared__ float kvs[64][68];
    __shared__ float nrm[64];
    __shared__ float kss[64];

    const int tid = threadIdx.x;
    const __half* Qbase = Qq + ((size_t)(b * Tt + t0)) * NCOL + hd * DKk;

    // load fp16 Q tile 64x64 -> fp32 smem (2 uint4 per thread)
#pragma unroll
    for (int p = 0; p < 2; p++) {
        int idx = tid + p * 256;
        int r = idx >> 3, c = (idx & 7) * 8;
        uint4 raw = *(const uint4*)&Qbase[(size_t)r * NCOL + c];
        const __half2* qh = (const __half2*)&raw;
#pragma unroll
        for (int j = 0; j < 4; j++) {
            float2 f = __half22float2(qh[j]);
            Qs[r][c + 2*j]     = f.x;
            Qs[r][c + 2*j + 1] = f.y;
        }
    }
    const float* kvb = kv + (size_t)bh * (DVv * DKk);
#pragma unroll
    for (int p = 0; p < 4; p++) {
        int idx = tid + p * 256;
        int r = idx >> 4, c = (idx & 15) << 2;
        *(float4*)&kvs[r][c] = *(const float4*)&kvb[(size_t)r * DKk + c];
    }
    if (tid < 64) kss[tid] = ksum[bh * DKk + tid];
    __syncthreads();

    if (tid < 64) {
        float s = 0.f;
#pragma unroll
        for (int d = 0; d < 64; d++) s += Qs[tid][d] * kss[d];
        nrm[tid] = 1.f / (s + EPSF);
    }
    __syncthreads();

    const int tm = (tid >> 4) << 2;
    const int tn = (tid & 15) << 2;
    float acc[4][4];
#pragma unroll
    for (int i = 0; i < 4; i++)
#pragma unroll
        for (int j = 0; j < 4; j++) acc[i][j] = 0.f;

#pragma unroll 16
    for (int d = 0; d < 64; d++) {
        float rq[4], rk[4];
#pragma unroll
        for (int i = 0; i < 4; i++) rq[i] = Qs[tm + i][d];
#pragma unroll
        for (int j = 0; j < 4; j++) rk[j] = kvs[tn + j][d];
#pragma unroll
        for (int i = 0; i < 4; i++)
#pragma unroll
            for (int j = 0; j < 4; j++)
                acc[i][j] += rq[i] * rk[j];
    }

#pragma unroll
    for (int i = 0; i < 4; i++) {
        float nr = nrm[tm + i];
        size_t base = ((size_t)(b * Tt + t0 + tm + i)) * NCOL + hd * DVv + tn;
        ((__half2*)(aout + base))[0] = __halves2half2(
            __float2half(acc[i][0] * nr), __float2half(acc[i][1] * nr));
        ((__half2*)(aout + base))[1] = __halves2half2(
            __float2half(acc[i][2] * nr), __float2half(acc[i][3] * nr));
    }
}

// ---------------- host ----------------
extern "C" void kernel_launch(void* const* d_in, const int* in_sizes, int n_in,
                              void* d_out, int out_size)
{
    (void)in_sizes; (void)n_in; (void)out_size;
    const float* query = (const float*)d_in[0];
    const float* key   = (const float*)d_in[1];
    const float* value = (const float*)d_in[2];
    const float* Wq    = (const float*)d_in[3];
    const float* bq    = (const float*)d_in[4];
    const float* Wk    = (const float*)d_in[5];
    const float* bk    = (const float*)d_in[6];
    const float* Wv    = (const float*)d_in[7];
    const float* bv    = (const float*)d_in[8];
    const float* Wo    = (const float*)d_in[9];
    const float* bo    = (const float*)d_in[10];
    float* out = (float*)d_out;

    __half *Xin, *Qh, *Kh, *Vh, *At, *Wt;
    float *kvpp, *kspp, *kvv, *kss;
    cudaGetSymbolAddress((void**)&Xin, g_Xin);
    cudaGetSymbolAddress((void**)&Qh,  g_Qh);
    cudaGetSymbolAddress((void**)&Kh,  g_Kh);
    cudaGetSymbolAddress((void**)&Vh,  g_Vh);
    cudaGetSymbolAddress((void**)&At,  g_At);
    cudaGetSymbolAddress((void**)&Wt,  g_Whi);
    cudaGetSymbolAddress((void**)&kvpp, g_kvp);
    cudaGetSymbolAddress((void**)&kspp, g_ksp);
    cudaGetSymbolAddress((void**)&kvv,  g_kv);
    cudaGetSymbolAddress((void**)&kss,  g_ksum);

    cudaFuncSetAttribute(gemm_mma<1,1>, cudaFuncAttributeMaxDynamicSharedMemorySize, SMEM_G);
    cudaFuncSetAttribute(gemm_mma<0,1>, cudaFuncAttributeMaxDynamicSharedMemorySize, SMEM_G);
    cudaFuncSetAttribute(gemm_mma<0,0>, cudaFuncAttributeMaxDynamicSharedMemorySize, SMEM_G);

    const size_t WSZ = (size_t)NCOL * KDIM;
    const size_t XSZ = (size_t)Mrows * KDIM;
    const int n4 = Mrows * KDIM / 4;

    // prep: weights (one launch) + inputs (one launch)
    wsplit4<<<dim3(NCOL / 32, KDIM / 32, 4), 256>>>(Wq, Wk, Wv, Wo, Wt);
    aconv3<<<dim3(n4 / 256, 3), 256>>>(query, key, value, Xin, n4);

    dim3 ggrid(NCOL / 128, Mrows / 128);   // (8, 128)

    // projections (fp16 out, phi fused for q,k)
    gemm_mma<1,1><<<ggrid, 256, SMEM_G>>>(Xin + 0 * XSZ, Wt + 0 * WSZ, bq, Qh);
    gemm_mma<1,1><<<ggrid, 256, SMEM_G>>>(Xin + 1 * XSZ, Wt + 1 * WSZ, bk, Kh);
    gemm_mma<0,1><<<ggrid, 256, SMEM_G>>>(Xin + 2 * XSZ, Wt + 2 * WSZ, bv, Vh);

    kv_partial<<<dim3(64, KVSPLIT), 256>>>(Kh, Vh, kvpp, kspp);
    kv_reduce<<<64, 256>>>(kvpp, kspp, kvv, kss);
    attn_tc<<<dim3(64, Tt / 64), 256>>>(Qh, kvv, kss, At);

    // output GEMM (fp32 out to d_out)
    gemm_mma<0,0><<<ggrid, 256, SMEM_G>>>(At, Wt + 3 * WSZ, bo, out);
}

// round 7
// speedup vs baseline: 4.2703x; 1.0360x over previous
#include <cuda_runtime.h>
#include <cuda_fp16.h>
#include <cstdint>
#include <cstddef>

#define Bb 4
#define Tt 4096
#define Hh 16
#define DKk 64
#define DVv 64
#define Mrows (Bb*Tt)          // 16384
#define NCOL 1024
#define KDIM 1024
#define EPSF 1e-6f
#define KVSPLIT 16

// ---------------- static scratch ----------------
__device__ __half g_Xin[3][(size_t)Mrows*KDIM];   // fp16 inputs (q,k,v source)
__device__ __half g_Qh[(size_t)Mrows*NCOL];       // fp16 projected Q (phi applied)
__device__ __half g_Kh[(size_t)Mrows*NCOL];
__device__ __half g_Vh[(size_t)Mrows*NCOL];
__device__ __half g_At[(size_t)Mrows*NCOL];       // fp16 attn output (final GEMM input)
__device__ __half g_Whi[4][(size_t)NCOL*KDIM];    // transposed [N,K], fp16
__device__ float g_kvp[KVSPLIT*64*DVv*DKk];
__device__ float g_ksp[KVSPLIT*64*DKk];
__device__ float g_kv[64*DVv*DKk];
__device__ float g_ksum[64*DKk];

// ---------------- PTX helpers (baseline ISA: sm_80 features only) -----------
__device__ __forceinline__ uint32_t s2u(const void* p){
    uint32_t a;
    asm("{ .reg .u64 t; cvta.to.shared.u64 t, %1; cvt.u32.u64 %0, t; }" : "=r"(a) : "l"(p));
    return a;
}
__device__ __forceinline__ void cpa16(uint32_t dst, const void* src){
    asm volatile("cp.async.cg.shared.global [%0], [%1], 16;" :: "r"(dst), "l"(src) : "memory");
}
__device__ __forceinline__ void cp_commit(){
    asm volatile("cp.async.commit_group;" ::: "memory");
}
template<int N>
__device__ __forceinline__ void cp_waitg(){
    asm volatile("cp.async.wait_group %0;" :: "n"(N) : "memory");
}
__device__ __forceinline__ void ldm4(uint32_t* r, uint32_t addr){
    asm volatile("ldmatrix.sync.aligned.m8n8.x4.shared.b16 {%0,%1,%2,%3}, [%4];"
        : "=r"(r[0]), "=r"(r[1]), "=r"(r[2]), "=r"(r[3]) : "r"(addr));
}
__device__ __forceinline__ void mma16816(float* c, const uint32_t* a, uint32_t b0, uint32_t b1){
    asm volatile("mma.sync.aligned.m16n8k16.row.col.f32.f16.f16.f32 "
        "{%0,%1,%2,%3}, {%4,%5,%6,%7}, {%8,%9}, {%0,%1,%2,%3};"
        : "+f"(c[0]), "+f"(c[1]), "+f"(c[2]), "+f"(c[3])
        : "r"(a[0]), "r"(a[1]), "r"(a[2]), "r"(a[3]), "r"(b0), "r"(b1));
}

// ---------------- HMMA GEMM core (1-pass): C = act(A @ W^T + bias) ----------
// Tile 128x128, k-chunk 32, 3-stage cp.async pipeline, 2 CTAs/SM.
#define RSTRIDE 80                 // bytes per 32-half row (16B pad: conflict-free ldmatrix)
#define TILE_SM (128*RSTRIDE)      // 10240 bytes per [128][32] tile
#define NKCH (KDIM/32)             // 32 k-chunks
#define NSTG 3
#define STGB (2*TILE_SM)
#define SMEM_G (NSTG*STGB)         // 61440 -> 2 CTAs/SM

template<int OUT16>
__device__ __forceinline__ void gemm_core(
    const __half* __restrict__ A, const __half* __restrict__ W,
    const float* __restrict__ bias, void* __restrict__ Cv,
    int act, char* smem)
{
    const uint32_t sb = s2u(smem);
    const int tid  = threadIdx.x;
    const int warp = tid >> 5, lane = tid & 31;
    const int wm = warp & 3, wn = warp >> 2;       // warp tile: 32(m) x 64(n)
    const int bm = blockIdx.y * 128, bn = blockIdx.x * 128;

    const int lrow = tid >> 1;          // 0..127
    const int lc   = (tid & 1) * 2;     // chunk 0 or 2

    const __half* gA = A + (size_t)(bm + lrow) * KDIM + lc * 8;
    const __half* gB = W + (size_t)(bn + lrow) * KDIM + lc * 8;
    const uint32_t dofs = lrow * RSTRIDE + lc * 16;

    float acc[2][8][4];
#pragma unroll
    for (int i = 0; i < 2; i++)
#pragma unroll
        for (int j = 0; j < 8; j++)
#pragma unroll
            for (int q = 0; q < 4; q++) acc[i][j][q] = 0.f;

#define ISSUE(kt, s) do {                                   \
        uint32_t st_ = sb + (s) * STGB + dofs;              \
        int ko_ = (kt) * 32;                                \
        cpa16(st_,                gA + ko_);                \
        cpa16(st_ + 16,           gA + ko_ + 8);            \
        cpa16(st_ + TILE_SM,      gB + ko_);                \
        cpa16(st_ + TILE_SM + 16, gB + ko_ + 8);            \
    } while (0)

#pragma unroll
    for (int s = 0; s < NSTG - 1; s++) { ISSUE(s, s); cp_commit(); }

    const int lm = lane & 15, lh = lane >> 4;

    for (int kt = 0; kt < NKCH; kt++) {
        cp_waitg<NSTG - 2>();
        __syncthreads();
        if (kt + NSTG - 1 < NKCH) ISSUE(kt + NSTG - 1, (kt + NSTG - 1) % NSTG);
        cp_commit();

        const uint32_t st = sb + (kt % NSTG) * STGB;
#pragma unroll
        for (int kk = 0; kk < 2; kk++) {
            const uint32_t kcol = kk * 32 + lh * 16;
            uint32_t ah[2][4], bh[4][4];
#pragma unroll
            for (int mt = 0; mt < 2; mt++) {
                uint32_t r = (uint32_t)(wm * 32 + mt * 16 + lm);
                ldm4(ah[mt], st + r * RSTRIDE + kcol);
            }
#pragma unroll
            for (int g = 0; g < 4; g++) {
                uint32_t r = (uint32_t)(wn * 64 + g * 16 + lm);
                ldm4(bh[g], st + TILE_SM + r * RSTRIDE + kcol);
            }
#pragma unroll
            for (int mt = 0; mt < 2; mt++)
#pragma unroll
                for (int g = 0; g < 4; g++) {
                    mma16816(acc[mt][2*g],   ah[mt], bh[g][0], bh[g][2]);
                    mma16816(acc[mt][2*g+1], ah[mt], bh[g][1], bh[g][3]);
                }
        }
    }
#undef ISSUE

    // epilogue: bias (+ELU+1), write fp16 or fp32
#pragma unroll
    for (int mt = 0; mt < 2; mt++) {
        const int row0 = bm + wm * 32 + mt * 16 + (lane >> 2);
#pragma unroll
        for (int ng = 0; ng < 8; ng++) {
            const int col = bn + wn * 64 + ng * 8 + 2 * (lane & 3);
            const float b0 = bias[col], b1 = bias[col + 1];
            float2 v0, v1;
            v0.x = acc[mt][ng][0] + b0;  v0.y = acc[mt][ng][1] + b1;
            v1.x = acc[mt][ng][2] + b0;  v1.y = acc[mt][ng][3] + b1;
            if (act) {
                v0.x = v0.x > 0.f ? v0.x + 1.f : __expf(v0.x);
                v0.y = v0.y > 0.f ? v0.y + 1.f : __expf(v0.y);
                v1.x = v1.x > 0.f ? v1.x + 1.f : __expf(v1.x);
                v1.y = v1.y > 0.f ? v1.y + 1.f : __expf(v1.y);
            }
            if (OUT16) {
                __half* C = (__half*)Cv;
                *(__half2*)&C[(size_t)row0 * NCOL + col] =
                    __halves2half2(__float2half(v0.x), __float2half(v0.y));
                *(__half2*)&C[(size_t)(row0 + 8) * NCOL + col] =
                    __halves2half2(__float2half(v1.x), __float2half(v1.y));
            } else {
                float* C = (float*)Cv;
                *(float2*)&C[(size_t)row0 * NCOL + col]       = v0;
                *(float2*)&C[(size_t)(row0 + 8) * NCOL + col] = v1;
            }
        }
    }
}

// merged QKV projections: z selects (input, weight, bias, output, act)
__global__ void __launch_bounds__(256, 2) gemm_qkv(
    const __half* __restrict__ Xin, const __half* __restrict__ Wt,
    const float* __restrict__ bq, const float* __restrict__ bk, const float* __restrict__ bv,
    __half* __restrict__ Qh, __half* __restrict__ Kh, __half* __restrict__ Vh)
{
    extern __shared__ __align__(128) char smem[];
    const int z = blockIdx.z;
    const __half* A = Xin + (size_t)z * Mrows * KDIM;
    const __half* W = Wt  + (size_t)z * NCOL * KDIM;
    const float* bias = (z == 0) ? bq : (z == 1) ? bk : bv;
    __half* C = (z == 0) ? Qh : (z == 1) ? Kh : Vh;
    gemm_core<1>(A, W, bias, C, (z < 2) ? 1 : 0, smem);
}

// output GEMM: fp32 out
__global__ void __launch_bounds__(256, 2) gemm_out(
    const __half* __restrict__ A, const __half* __restrict__ W,
    const float* __restrict__ bias, float* __restrict__ C)
{
    extern __shared__ __align__(128) char smem[];
    gemm_core<0>(A, W, bias, C, 0, smem);
}

// ---------------- fp32 -> fp16 for q,k,v inputs (one launch) ----------------
__global__ void __launch_bounds__(256) aconv3(const float* __restrict__ q,
                                              const float* __restrict__ k,
                                              const float* __restrict__ v,
                                              __half* __restrict__ dst, int n4)
{
    const float* src = (blockIdx.y == 0) ? q : (blockIdx.y == 1) ? k : v;
    __half* d = dst + (size_t)blockIdx.y * Mrows * KDIM;
    int i = blockIdx.x * 256 + threadIdx.x;
    if (i >= n4) return;
    float4 val = ((const float4*)src)[i];
    __half2* H = (__half2*)d;
    H[2*i]   = __halves2half2(__float2half(val.x), __float2half(val.y));
    H[2*i+1] = __halves2half2(__float2half(val.z), __float2half(val.w));
}

// ---------------- weight transpose + fp16: W[K,N] -> Wt[N,K] (one launch) ---
__global__ void __launch_bounds__(256) wsplit4(const float* __restrict__ W0,
                                               const float* __restrict__ W1,
                                               const float* __restrict__ W2,
                                               const float* __restrict__ W3,
                                               __half* __restrict__ dst)
{
    const int wsel = blockIdx.z;
    const float* W = (wsel == 0) ? W0 : (wsel == 1) ? W1 : (wsel == 2) ? W2 : W3;
    __half* thi = dst + (size_t)wsel * NCOL * KDIM;

    __shared__ float tile[32][33];
    const int n0 = blockIdx.x * 32, k0 = blockIdx.y * 32;
    const int tx = threadIdx.x & 31, ty = threadIdx.x >> 5;
#pragma unroll
    for (int r = ty; r < 32; r += 8)
        tile[r][tx] = W[(size_t)(k0 + r) * NCOL + n0 + tx];
    __syncthreads();
#pragma unroll
    for (int r = ty; r < 32; r += 8)
        thi[(size_t)(n0 + r) * KDIM + k0 + tx] = __float2half(tile[tx][r]);
}

// ---------------- kv partial over fp16 K,V ----------------------------------
__global__ void __launch_bounds__(256) kv_partial(const __half* __restrict__ Kq,
                                                  const __half* __restrict__ Vq,
                                                  float* __restrict__ kvp, float* __restrict__ ksp)
{
    const int bh = blockIdx.x, sp = blockIdx.y;
    const int b = bh >> 4, hd = bh & 15;
    const int TSEG = Tt / KVSPLIT;          // 256
    __shared__ float Ks[32][64];
    __shared__ float Vs[32][64];
    const int tid = threadIdx.x;
    const int ty = tid >> 4, tx = tid & 15;
    const __half* Kb = Kq + ((size_t)b * Tt + sp * TSEG) * NCOL + hd * DKk;
    const __half* Vb = Vq + ((size_t)b * Tt + sp * TSEG) * NCOL + hd * DVv;

    const int lr = tid >> 3;            // 0..31
    const int lcc = (tid & 7) * 8;      // 0..56

    float acc[4][4];
#pragma unroll
    for (int i = 0; i < 4; i++)
#pragma unroll
        for (int j = 0; j < 4; j++) acc[i][j] = 0.f;
    float ks = 0.f;

    for (int t0 = 0; t0 < TSEG; t0 += 32) {
        {
            uint4 kraw = *(const uint4*)&Kb[(size_t)(t0 + lr) * NCOL + lcc];
            uint4 vraw = *(const uint4*)&Vb[(size_t)(t0 + lr) * NCOL + lcc];
            const __half2* kh = (const __half2*)&kraw;
            const __half2* vh = (const __half2*)&vraw;
#pragma unroll
            for (int j = 0; j < 4; j++) {
                float2 kf = __half22float2(kh[j]);
                float2 vf = __half22float2(vh[j]);
                Ks[lr][lcc + 2*j]     = kf.x;
                Ks[lr][lcc + 2*j + 1] = kf.y;
                Vs[lr][lcc + 2*j]     = vf.x;
                Vs[lr][lcc + 2*j + 1] = vf.y;
            }
        }
        __syncthreads();
#pragma unroll 8
        for (int t = 0; t < 32; t++) {
            float rv[4], rk[4];
#pragma unroll
            for (int i = 0; i < 4; i++) rv[i] = Vs[t][ty * 4 + i];
#pragma unroll
            for (int j = 0; j < 4; j++) rk[j] = Ks[t][tx * 4 + j];
#pragma unroll
            for (int i = 0; i < 4; i++)
#pragma unroll
                for (int j = 0; j < 4; j++)
                    acc[i][j] += rv[i] * rk[j];
        }
        if (tid < 64) {
#pragma unroll
            for (int t = 0; t < 32; t++) ks += Ks[t][tid];
        }
        __syncthreads();
    }

    float* o = kvp + (size_t)(sp * 64 + bh) * (DVv * DKk);
#pragma unroll
    for (int i = 0; i < 4; i++) {
        float4 v;
        v.x = acc[i][0]; v.y = acc[i][1]; v.z = acc[i][2]; v.w = acc[i][3];
        *(float4*)&o[(ty * 4 + i) * DKk + tx * 4] = v;
    }
    if (tid < 64) ksp[(sp * 64 + bh) * DKk + tid] = ks;
}

__global__ void __launch_bounds__(256) kv_reduce(const float* __restrict__ kvp, const float* __restrict__ ksp,
                                                 float* __restrict__ kv, float* __restrict__ ksum)
{
    const int bh = blockIdx.x, tid = threadIdx.x;
    for (int i = tid; i < DVv * DKk; i += 256) {
        float s = 0.f;
#pragma unroll
        for (int y = 0; y < KVSPLIT; y++) s += kvp[(size_t)(y * 64 + bh) * (DVv * DKk) + i];
        kv[(size_t)bh * (DVv * DKk) + i] = s;
    }
    if (tid < DKk) {
        float s = 0.f;
#pragma unroll
        for (int y = 0; y < KVSPLIT; y++) s += ksp[(y * 64 + bh) * DKk + tid];
        ksum[bh * DKk + tid] = s;
    }
}

// ---------------- attn: fp16 Q in, fp16 out ---------------------------------
__global__ void __launch_bounds__(256) attn_tc(
    const __half* __restrict__ Qq, const float* __restrict__ kv,
    const float* __restrict__ ksum, __half* __restrict__ aout)
{
    const int bh = blockIdx.x;
    const int b = bh >> 4, hd = bh & 15;
    const int t0 = blockIdx.y * 64;

    __shared__ float Qs[64][68];
    __shared__ float kvs[64][68];
    __shared__ float nrm[64];
    __shared__ float kss[64];

    const int tid = threadIdx.x;
    const __half* Qbase = Qq + ((size_t)(b * Tt + t0)) * NCOL + hd * DKk;

#pragma unroll
    for (int p = 0; p < 2; p++) {
        int idx = tid + p * 256;
        int r = idx >> 3, c = (idx & 7) * 8;
        uint4 raw = *(const uint4*)&Qbase[(size_t)r * NCOL + c];
        const __half2* qh = (const __half2*)&raw;
#pragma unroll
        for (int j = 0; j < 4; j++) {
            float2 f = __half22float2(qh[j]);
            Qs[r][c + 2*j]     = f.x;
            Qs[r][c + 2*j + 1] = f.y;
        }
    }
    const float* kvb = kv + (size_t)bh * (DVv * DKk);
#pragma unroll
    for (int p = 0; p < 4; p++) {
        int idx = tid + p * 256;
        int r = idx >> 4, c = (idx & 15) << 2;
        *(float4*)&kvs[r][c] = *(const float4*)&kvb[(size_t)r * DKk + c];
    }
    if (tid < 64) kss[tid] = ksum[bh * DKk + tid];
    __syncthreads();

    if (tid < 64) {
        float s = 0.f;
#pragma unroll
        for (int d = 0; d < 64; d++) s += Qs[tid][d] * kss[d];
        nrm[tid] = 1.f / (s + EPSF);
    }
    __syncthreads();

    const int tm = (tid >> 4) << 2;
    const int tn = (tid & 15) << 2;
    float acc[4][4];
#pragma unroll
    for (int i = 0; i < 4; i++)
#pragma unroll
        for (int j = 0; j < 4; j++) acc[i][j] = 0.f;

#pragma unroll 16
    for (int d = 0; d < 64; d++) {
        float rq[4], rk[4];
#pragma unroll
        for (int i = 0; i < 4; i++) rq[i] = Qs[tm + i][d];
#pragma unroll
        for (int j = 0; j < 4; j++) rk[j] = kvs[tn + j][d];
#pragma unroll
        for (int i = 0; i < 4; i++)
#pragma unroll
            for (int j = 0; j < 4; j++)
                acc[i][j] += rq[i] * rk[j];
    }

#pragma unroll
    for (int i = 0; i < 4; i++) {
        float nr = nrm[tm + i];
        size_t base = ((size_t)(b * Tt + t0 + tm + i)) * NCOL + hd * DVv + tn;
        ((__half2*)(aout + base))[0] = __halves2half2(
            __float2half(acc[i][0] * nr), __float2half(acc[i][1] * nr));
        ((__half2*)(aout + base))[1] = __halves2half2(
            __float2half(acc[i][2] * nr), __float2half(acc[i][3] * nr));
    }
}

// ---------------- host ----------------
extern "C" void kernel_launch(void* const* d_in, const int* in_sizes, int n_in,
                              void* d_out, int out_size)
{
    (void)in_sizes; (void)n_in; (void)out_size;
    const float* query = (const float*)d_in[0];
    const float* key   = (const float*)d_in[1];
    const float* value = (const float*)d_in[2];
    const float* Wq    = (const float*)d_in[3];
    const float* bq    = (const float*)d_in[4];
    const float* Wk    = (const float*)d_in[5];
    const float* bk    = (const float*)d_in[6];
    const float* Wv    = (const float*)d_in[7];
    const float* bv    = (const float*)d_in[8];
    const float* Wo    = (const float*)d_in[9];
    const float* bo    = (const float*)d_in[10];
    float* out = (float*)d_out;

    __half *Xin, *Qh, *Kh, *Vh, *At, *Wt;
    float *kvpp, *kspp, *kvv, *kss;
    cudaGetSymbolAddress((void**)&Xin, g_Xin);
    cudaGetSymbolAddress((void**)&Qh,  g_Qh);
    cudaGetSymbolAddress((void**)&Kh,  g_Kh);
    cudaGetSymbolAddress((void**)&Vh,  g_Vh);
    cudaGetSymbolAddress((void**)&At,  g_At);
    cudaGetSymbolAddress((void**)&Wt,  g_Whi);
    cudaGetSymbolAddress((void**)&kvpp, g_kvp);
    cudaGetSymbolAddress((void**)&kspp, g_ksp);
    cudaGetSymbolAddress((void**)&kvv,  g_kv);
    cudaGetSymbolAddress((void**)&kss,  g_ksum);

    cudaFuncSetAttribute(gemm_qkv, cudaFuncAttributeMaxDynamicSharedMemorySize, SMEM_G);
    cudaFuncSetAttribute(gemm_out, cudaFuncAttributeMaxDynamicSharedMemorySize, SMEM_G);

    const size_t WSZ = (size_t)NCOL * KDIM;
    const int n4 = Mrows * KDIM / 4;

    // prep: weights (one launch) + inputs (one launch)
    wsplit4<<<dim3(NCOL / 32, KDIM / 32, 4), 256>>>(Wq, Wk, Wv, Wo, Wt);
    aconv3<<<dim3(n4 / 256, 3), 256>>>(query, key, value, Xin, n4);

    // merged QKV projections (fp16 out, phi fused for q,k)
    gemm_qkv<<<dim3(NCOL / 128, Mrows / 128, 3), 256, SMEM_G>>>(
        Xin, Wt, bq, bk, bv, Qh, Kh, Vh);

    kv_partial<<<dim3(64, KVSPLIT), 256>>>(Kh, Vh, kvpp, kspp);
    kv_reduce<<<64, 256>>>(kvpp, kspp, kvv, kss);
    attn_tc<<<dim3(64, Tt / 64), 256>>>(Qh, kvv, kss, At);

    // output GEMM (fp32 out to d_out)
    gemm_out<<<dim3(NCOL / 128, Mrows / 128), 256, SMEM_G>>>(At, Wt + 3 * WSZ, bo, out);
}

// round 8
// speedup vs baseline: 5.6350x; 1.3196x over previous
#include <cuda_runtime.h>
#include <cuda_fp16.h>
#include <cstdint>
#include <cstddef>

#define Bb 4
#define Tt 4096
#define Hh 16
#define DKk 64
#define DVv 64
#define Mrows (Bb*Tt)          // 16384
#define NCOL 1024
#define KDIM 1024
#define EPSF 1e-6f
#define KVSPLIT 16
#define TSEG (Tt/KVSPLIT)      // 256

// ---------------- static scratch ----------------
__device__ __half g_Xin[3][(size_t)Mrows*KDIM];   // fp16 inputs (q,k,v source)
__device__ __half g_Qh[(size_t)Mrows*NCOL];       // fp16 projected Q (phi applied)
__device__ __half g_Kh[(size_t)Mrows*NCOL];
__device__ __half g_Vh[(size_t)Mrows*NCOL];
__device__ __half g_At[(size_t)Mrows*NCOL];       // fp16 attn output (final GEMM input)
__device__ __half g_Whi[4][(size_t)NCOL*KDIM];    // transposed [N,K], fp16
__device__ float g_kvp[KVSPLIT*64*DVv*DKk];
__device__ float g_ksp[KVSPLIT*64*DKk];
__device__ __half g_kvh[64*DVv*DKk];              // fp16 kv (attn GEMM B operand)
__device__ float g_ksum[64*DKk];

// ---------------- PTX helpers (baseline ISA: sm_80 features only) -----------
__device__ __forceinline__ uint32_t s2u(const void* p){
    uint32_t a;
    asm("{ .reg .u64 t; cvta.to.shared.u64 t, %1; cvt.u32.u64 %0, t; }" : "=r"(a) : "l"(p));
    return a;
}
__device__ __forceinline__ void cpa16(uint32_t dst, const void* src){
    asm volatile("cp.async.cg.shared.global [%0], [%1], 16;" :: "r"(dst), "l"(src) : "memory");
}
__device__ __forceinline__ void cp_commit(){
    asm volatile("cp.async.commit_group;" ::: "memory");
}
template<int N>
__device__ __forceinline__ void cp_waitg(){
    asm volatile("cp.async.wait_group %0;" :: "n"(N) : "memory");
}
__device__ __forceinline__ void ldm4(uint32_t* r, uint32_t addr){
    asm volatile("ldmatrix.sync.aligned.m8n8.x4.shared.b16 {%0,%1,%2,%3}, [%4];"
        : "=r"(r[0]), "=r"(r[1]), "=r"(r[2]), "=r"(r[3]) : "r"(addr));
}
__device__ __forceinline__ void ldm4t(uint32_t* r, uint32_t addr){
    asm volatile("ldmatrix.sync.aligned.m8n8.x4.trans.shared.b16 {%0,%1,%2,%3}, [%4];"
        : "=r"(r[0]), "=r"(r[1]), "=r"(r[2]), "=r"(r[3]) : "r"(addr));
}
__device__ __forceinline__ void mma16816(float* c, const uint32_t* a, uint32_t b0, uint32_t b1){
    asm volatile("mma.sync.aligned.m16n8k16.row.col.f32.f16.f16.f32 "
        "{%0,%1,%2,%3}, {%4,%5,%6,%7}, {%8,%9}, {%0,%1,%2,%3};"
        : "+f"(c[0]), "+f"(c[1]), "+f"(c[2]), "+f"(c[3])
        : "r"(a[0]), "r"(a[1]), "r"(a[2]), "r"(a[3]), "r"(b0), "r"(b1));
}

// ---------------- HMMA GEMM core (1-pass): C = act(A @ W^T + bias) ----------
#define RSTRIDE 80                 // bytes per 32-half row
#define TILE_SM (128*RSTRIDE)      // 10240 bytes per [128][32] tile
#define NKCH (KDIM/32)             // 32 k-chunks
#define NSTG 3
#define STGB (2*TILE_SM)
#define SMEM_G (NSTG*STGB)         // 61440 -> 2 CTAs/SM

template<int OUT16>
__device__ __forceinline__ void gemm_core(
    const __half* __restrict__ A, const __half* __restrict__ W,
    const float* __restrict__ bias, void* __restrict__ Cv,
    int act, char* smem)
{
    const uint32_t sb = s2u(smem);
    const int tid  = threadIdx.x;
    const int warp = tid >> 5, lane = tid & 31;
    const int wm = warp & 3, wn = warp >> 2;
    const int bm = blockIdx.y * 128, bn = blockIdx.x * 128;

    const int lrow = tid >> 1;
    const int lc   = (tid & 1) * 2;

    const __half* gA = A + (size_t)(bm + lrow) * KDIM + lc * 8;
    const __half* gB = W + (size_t)(bn + lrow) * KDIM + lc * 8;
    const uint32_t dofs = lrow * RSTRIDE + lc * 16;

    float acc[2][8][4];
#pragma unroll
    for (int i = 0; i < 2; i++)
#pragma unroll
        for (int j = 0; j < 8; j++)
#pragma unroll
            for (int q = 0; q < 4; q++) acc[i][j][q] = 0.f;

#define ISSUE(kt, s) do {                                   \
        uint32_t st_ = sb + (s) * STGB + dofs;              \
        int ko_ = (kt) * 32;                                \
        cpa16(st_,                gA + ko_);                \
        cpa16(st_ + 16,           gA + ko_ + 8);            \
        cpa16(st_ + TILE_SM,      gB + ko_);                \
        cpa16(st_ + TILE_SM + 16, gB + ko_ + 8);            \
    } while (0)

#pragma unroll
    for (int s = 0; s < NSTG - 1; s++) { ISSUE(s, s); cp_commit(); }

    const int lm = lane & 15, lh = lane >> 4;

    for (int kt = 0; kt < NKCH; kt++) {
        cp_waitg<NSTG - 2>();
        __syncthreads();
        if (kt + NSTG - 1 < NKCH) ISSUE(kt + NSTG - 1, (kt + NSTG - 1) % NSTG);
        cp_commit();

        const uint32_t st = sb + (kt % NSTG) * STGB;
#pragma unroll
        for (int kk = 0; kk < 2; kk++) {
            const uint32_t kcol = kk * 32 + lh * 16;
            uint32_t ah[2][4], bh[4][4];
#pragma unroll
            for (int mt = 0; mt < 2; mt++) {
                uint32_t r = (uint32_t)(wm * 32 + mt * 16 + lm);
                ldm4(ah[mt], st + r * RSTRIDE + kcol);
            }
#pragma unroll
            for (int g = 0; g < 4; g++) {
                uint32_t r = (uint32_t)(wn * 64 + g * 16 + lm);
                ldm4(bh[g], st + TILE_SM + r * RSTRIDE + kcol);
            }
#pragma unroll
            for (int mt = 0; mt < 2; mt++)
#pragma unroll
                for (int g = 0; g < 4; g++) {
                    mma16816(acc[mt][2*g],   ah[mt], bh[g][0], bh[g][2]);
                    mma16816(acc[mt][2*g+1], ah[mt], bh[g][1], bh[g][3]);
                }
        }
    }
#undef ISSUE

#pragma unroll
    for (int mt = 0; mt < 2; mt++) {
        const int row0 = bm + wm * 32 + mt * 16 + (lane >> 2);
#pragma unroll
        for (int ng = 0; ng < 8; ng++) {
            const int col = bn + wn * 64 + ng * 8 + 2 * (lane & 3);
            const float b0 = bias[col], b1 = bias[col + 1];
            float2 v0, v1;
            v0.x = acc[mt][ng][0] + b0;  v0.y = acc[mt][ng][1] + b1;
            v1.x = acc[mt][ng][2] + b0;  v1.y = acc[mt][ng][3] + b1;
            if (act) {
                v0.x = v0.x > 0.f ? v0.x + 1.f : __expf(v0.x);
                v0.y = v0.y > 0.f ? v0.y + 1.f : __expf(v0.y);
                v1.x = v1.x > 0.f ? v1.x + 1.f : __expf(v1.x);
                v1.y = v1.y > 0.f ? v1.y + 1.f : __expf(v1.y);
            }
            if (OUT16) {
                __half* C = (__half*)Cv;
                *(__half2*)&C[(size_t)row0 * NCOL + col] =
                    __halves2half2(__float2half(v0.x), __float2half(v0.y));
                *(__half2*)&C[(size_t)(row0 + 8) * NCOL + col] =
                    __halves2half2(__float2half(v1.x), __float2half(v1.y));
            } else {
                float* C = (float*)Cv;
                *(float2*)&C[(size_t)row0 * NCOL + col]       = v0;
                *(float2*)&C[(size_t)(row0 + 8) * NCOL + col] = v1;
            }
        }
    }
}

__global__ void __launch_bounds__(256, 2) gemm_qkv(
    const __half* __restrict__ Xin, const __half* __restrict__ Wt,
    const float* __restrict__ bq, const float* __restrict__ bk, const float* __restrict__ bv,
    __half* __restrict__ Qh, __half* __restrict__ Kh, __half* __restrict__ Vh)
{
    extern __shared__ __align__(128) char smem[];
    const int z = blockIdx.z;
    const __half* A = Xin + (size_t)z * Mrows * KDIM;
    const __half* W = Wt  + (size_t)z * NCOL * KDIM;
    const float* bias = (z == 0) ? bq : (z == 1) ? bk : bv;
    __half* C = (z == 0) ? Qh : (z == 1) ? Kh : Vh;
    gemm_core<1>(A, W, bias, C, (z < 2) ? 1 : 0, smem);
}

__global__ void __launch_bounds__(256, 2) gemm_out(
    const __half* __restrict__ A, const __half* __restrict__ W,
    const float* __restrict__ bias, float* __restrict__ C)
{
    extern __shared__ __align__(128) char smem[];
    gemm_core<0>(A, W, bias, C, 0, smem);
}

// ---------------- fp32 -> fp16 for q,k,v inputs (one launch) ----------------
__global__ void __launch_bounds__(256) aconv3(const float* __restrict__ q,
                                              const float* __restrict__ k,
                                              const float* __restrict__ v,
                                              __half* __restrict__ dst, int n4)
{
    const float* src = (blockIdx.y == 0) ? q : (blockIdx.y == 1) ? k : v;
    __half* d = dst + (size_t)blockIdx.y * Mrows * KDIM;
    int i = blockIdx.x * 256 + threadIdx.x;
    if (i >= n4) return;
    float4 val = ((const float4*)src)[i];
    __half2* H = (__half2*)d;
    H[2*i]   = __halves2half2(__float2half(val.x), __float2half(val.y));
    H[2*i+1] = __halves2half2(__float2half(val.z), __float2half(val.w));
}

// ---------------- weight transpose + fp16: W[K,N] -> Wt[N,K] (one launch) ---
__global__ void __launch_bounds__(256) wsplit4(const float* __restrict__ W0,
                                               const float* __restrict__ W1,
                                               const float* __restrict__ W2,
                                               const float* __restrict__ W3,
                                               __half* __restrict__ dst)
{
    const int wsel = blockIdx.z;
    const float* W = (wsel == 0) ? W0 : (wsel == 1) ? W1 : (wsel == 2) ? W2 : W3;
    __half* thi = dst + (size_t)wsel * NCOL * KDIM;

    __shared__ float tile[32][33];
    const int n0 = blockIdx.x * 32, k0 = blockIdx.y * 32;
    const int tx = threadIdx.x & 31, ty = threadIdx.x >> 5;
#pragma unroll
    for (int r = ty; r < 32; r += 8)
        tile[r][tx] = W[(size_t)(k0 + r) * NCOL + n0 + tx];
    __syncthreads();
#pragma unroll
    for (int r = ty; r < 32; r += 8)
        thi[(size_t)(n0 + r) * KDIM + k0 + tx] = __float2half(tile[tx][r]);
}

// ---------------- kv via tensor cores: kv[dv,dk] = sum_t V[t,dv] K[t,dk] ----
// smem rows padded to 144B (72 halves) -> conflict-free ldmatrix.
#define KVROW 144
#define KVTILE (32*KVROW)          // 4608 bytes per 32x64 fp16 tile

__global__ void __launch_bounds__(128) kv_mma(const __half* __restrict__ Kq,
                                              const __half* __restrict__ Vq,
                                              float* __restrict__ kvp, float* __restrict__ ksp)
{
    __shared__ __align__(16) char sm[2 * 2 * KVTILE];   // [stage][K,V]
    const uint32_t sb = s2u(sm);
    const int bh = blockIdx.x, sp = blockIdx.y;
    const int b = bh >> 4, hd = bh & 15;
    const int tid = threadIdx.x, warp = tid >> 5, lane = tid & 31;

    const __half* Kb = Kq + ((size_t)b * Tt + sp * TSEG) * NCOL + hd * DKk;
    const __half* Vb = Vq + ((size_t)b * Tt + sp * TSEG) * NCOL + hd * DVv;

    float acc[8][4];
#pragma unroll
    for (int j = 0; j < 8; j++)
#pragma unroll
        for (int q = 0; q < 4; q++) acc[j][q] = 0.f;
    float ks = 0.f;

#define KVISSUE(t0, s) do {                                            \
        uint32_t base_ = sb + (s) * (2 * KVTILE);                      \
        _Pragma("unroll")                                              \
        for (int p = 0; p < 2; p++) {                                  \
            int idx_ = tid + p * 128;                                  \
            int r_ = idx_ >> 3, cb_ = idx_ & 7;                        \
            cpa16(base_ + r_ * KVROW + cb_ * 16,                       \
                  Kb + (size_t)((t0) + r_) * NCOL + cb_ * 8);          \
            cpa16(base_ + KVTILE + r_ * KVROW + cb_ * 16,              \
                  Vb + (size_t)((t0) + r_) * NCOL + cb_ * 8);          \
        }                                                              \
    } while (0)

    const int NT = TSEG / 32;   // 8
    KVISSUE(0, 0);  cp_commit();
    KVISSUE(32, 1); cp_commit();

    for (int i = 0; i < NT; i++) {
        if (i == NT - 1) cp_waitg<0>(); else cp_waitg<1>();
        __syncthreads();

        const int s = i & 1;
        const uint32_t Kst = sb + s * (2 * KVTILE);
        const uint32_t Vst = Kst + KVTILE;
#pragma unroll
        for (int kk = 0; kk < 2; kk++) {
            const uint32_t rowoff = (kk * 16 + (lane & 15)) * KVROW + (lane >> 4) * 16;
            uint32_t ar[4];
            ldm4t(ar, Vst + rowoff + warp * 32);          // A = V^T (m=dv,k=t)
            uint32_t a2[4] = { ar[0], ar[2], ar[1], ar[3] };  // trans reorder
#pragma unroll
            for (int g = 0; g < 4; g++) {
                uint32_t br[4];
                ldm4t(br, Kst + rowoff + g * 32);          // B = K^T (n=dk,k=t)
                mma16816(acc[2*g],   a2, br[0], br[1]);
                mma16816(acc[2*g+1], a2, br[2], br[3]);
            }
        }
        if (tid < 64) {
#pragma unroll
            for (int t = 0; t < 32; t++)
                ks += __half2float(*(const __half*)(sm + s * (2 * KVTILE) + t * KVROW + tid * 2));
        }
        __syncthreads();
        if (i + 2 < NT) { KVISSUE((i + 2) * 32, s); cp_commit(); }
    }
#undef KVISSUE

    float* o = kvp + (size_t)(sp * 64 + bh) * (DVv * DKk);
    const int r = warp * 16 + (lane >> 2);
    const int c = 2 * (lane & 3);
#pragma unroll
    for (int j = 0; j < 8; j++) {
        const int n0 = (j >> 1) * 16 + (j & 1) * 8 + c;
        float2 lo; lo.x = acc[j][0]; lo.y = acc[j][1];
        float2 hi; hi.x = acc[j][2]; hi.y = acc[j][3];
        *(float2*)&o[r * DKk + n0]       = lo;
        *(float2*)&o[(r + 8) * DKk + n0] = hi;
    }
    if (tid < 64) ksp[(sp * 64 + bh) * DKk + tid] = ks;
}

// reduce partials -> fp16 kv + fp32 ksum
__global__ void __launch_bounds__(256) kv_reduce(const float* __restrict__ kvp, const float* __restrict__ ksp,
                                                 __half* __restrict__ kvh, float* __restrict__ ksum)
{
    const int bh = blockIdx.x, tid = threadIdx.x;
    for (int i = tid; i < DVv * DKk; i += 256) {
        float s = 0.f;
#pragma unroll
        for (int y = 0; y < KVSPLIT; y++) s += kvp[(size_t)(y * 64 + bh) * (DVv * DKk) + i];
        kvh[(size_t)bh * (DVv * DKk) + i] = __float2half(s);
    }
    if (tid < DKk) {
        float s = 0.f;
#pragma unroll
        for (int y = 0; y < KVSPLIT; y++) s += ksp[(y * 64 + bh) * DKk + tid];
        ksum[bh * DKk + tid] = s;
    }
}

// ---------------- attn via tensor cores: attn[t,dv] = nrm * Q[t,:] . kv[dv,:]
__global__ void __launch_bounds__(128) attn_mma(
    const __half* __restrict__ Qq, const __half* __restrict__ kvh,
    const float* __restrict__ ksum, __half* __restrict__ aout)
{
    __shared__ __align__(16) __half Qs[128 * 72];
    __shared__ __align__(16) __half Bs[64 * 72];
    __shared__ float kss[64];
    __shared__ float nrm[128];

    const int bh = blockIdx.x;
    const int b = bh >> 4, hd = bh & 15;
    const int t0 = blockIdx.y * 128;
    const int tid = threadIdx.x, warp = tid >> 5, lane = tid & 31;

    const __half* Qb = Qq + ((size_t)(b * Tt + t0)) * NCOL + hd * DKk;
#pragma unroll
    for (int p = 0; p < 8; p++) {
        int idx = tid + p * 128;
        int r = idx >> 3, cb = idx & 7;
        *(uint4*)&Qs[r * 72 + cb * 8] = *(const uint4*)&Qb[(size_t)r * NCOL + cb * 8];
    }
    const __half* kb = kvh + (size_t)bh * (DVv * DKk);
#pragma unroll
    for (int p = 0; p < 4; p++) {
        int idx = tid + p * 128;
        int r = idx >> 3, cb = idx & 7;
        *(uint4*)&Bs[r * 72 + cb * 8] = *(const uint4*)&kb[r * DKk + cb * 8];
    }
    if (tid < 64) kss[tid] = ksum[bh * DKk + tid];
    __syncthreads();

    // per-row normalizer (fp32)
    {
        float s = 0.f;
#pragma unroll
        for (int d = 0; d < 64; d++) s += __half2float(Qs[tid * 72 + d]) * kss[d];
        nrm[tid] = 1.f / (s + EPSF);
    }

    const uint32_t sq = s2u(Qs), sbv = s2u(Bs);
    float acc[2][8][4];
#pragma unroll
    for (int i = 0; i < 2; i++)
#pragma unroll
        for (int j = 0; j < 8; j++)
#pragma unroll
            for (int q = 0; q < 4; q++) acc[i][j][q] = 0.f;

#pragma unroll
    for (int k0 = 0; k0 < 64; k0 += 16) {
        const uint32_t coloff = (k0 + (lane >> 4) * 8) * 2;
        uint32_t a[2][4];
#pragma unroll
        for (int mt = 0; mt < 2; mt++)
            ldm4(a[mt], sq + (warp * 32 + mt * 16 + (lane & 15)) * 144 + coloff);
#pragma unroll
        for (int g = 0; g < 4; g++) {
            uint32_t br[4];
            ldm4(br, sbv + (g * 16 + (lane & 15)) * 144 + coloff);
#pragma unroll
            for (int mt = 0; mt < 2; mt++) {
                mma16816(acc[mt][2*g],   a[mt], br[0], br[2]);
                mma16816(acc[mt][2*g+1], a[mt], br[1], br[3]);
            }
        }
    }
    __syncthreads();   // nrm visibility across warps

#pragma unroll
    for (int mt = 0; mt < 2; mt++) {
        const int r = warp * 32 + mt * 16 + (lane >> 2);
        const float n0r = nrm[r], n1r = nrm[r + 8];
        const size_t row0 = ((size_t)(b * Tt + t0 + r)) * NCOL + hd * DVv;
        const size_t row1 = row0 + 8 * NCOL;
#pragma unroll
        for (int j = 0; j < 8; j++) {
            const int n0 = (j >> 1) * 16 + (j & 1) * 8 + 2 * (lane & 3);
            *(__half2*)&aout[row0 + n0] = __halves2half2(
                __float2half(acc[mt][j][0] * n0r), __float2half(acc[mt][j][1] * n0r));
            *(__half2*)&aout[row1 + n0] = __halves2half2(
                __float2half(acc[mt][j][2] * n1r), __float2half(acc[mt][j][3] * n1r));
        }
    }
}

// ---------------- host ----------------
extern "C" void kernel_launch(void* const* d_in, const int* in_sizes, int n_in,
                              void* d_out, int out_size)
{
    (void)in_sizes; (void)n_in; (void)out_size;
    const float* query = (const float*)d_in[0];
    const float* key   = (const float*)d_in[1];
    const float* value = (const float*)d_in[2];
    const float* Wq    = (const float*)d_in[3];
    const float* bq    = (const float*)d_in[4];
    const float* Wk    = (const float*)d_in[5];
    const float* bk    = (const float*)d_in[6];
    const float* Wv    = (const float*)d_in[7];
    const float* bv    = (const float*)d_in[8];
    const float* Wo    = (const float*)d_in[9];
    const float* bo    = (const float*)d_in[10];
    float* out = (float*)d_out;

    __half *Xin, *Qh, *Kh, *Vh, *At, *Wt, *kvh;
    float *kvpp, *kspp, *kss;
    cudaGetSymbolAddress((void**)&Xin, g_Xin);
    cudaGetSymbolAddress((void**)&Qh,  g_Qh);
    cudaGetSymbolAddress((void**)&Kh,  g_Kh);
    cudaGetSymbolAddress((void**)&Vh,  g_Vh);
    cudaGetSymbolAddress((void**)&At,  g_At);
    cudaGetSymbolAddress((void**)&Wt,  g_Whi);
    cudaGetSymbolAddress((void**)&kvh, g_kvh);
    cudaGetSymbolAddress((void**)&kvpp, g_kvp);
    cudaGetSymbolAddress((void**)&kspp, g_ksp);
    cudaGetSymbolAddress((void**)&kss,  g_ksum);

    cudaFuncSetAttribute(gemm_qkv, cudaFuncAttributeMaxDynamicSharedMemorySize, SMEM_G);
    cudaFuncSetAttribute(gemm_out, cudaFuncAttributeMaxDynamicSharedMemorySize, SMEM_G);

    const size_t WSZ = (size_t)NCOL * KDIM;
    const int n4 = Mrows * KDIM / 4;

    wsplit4<<<dim3(NCOL / 32, KDIM / 32, 4), 256>>>(Wq, Wk, Wv, Wo, Wt);
    aconv3<<<dim3(n4 / 256, 3), 256>>>(query, key, value, Xin, n4);

    gemm_qkv<<<dim3(NCOL / 128, Mrows / 128, 3), 256, SMEM_G>>>(
        Xin, Wt, bq, bk, bv, Qh, Kh, Vh);

    kv_mma<<<dim3(64, KVSPLIT), 128>>>(Kh, Vh, kvpp, kspp);
    kv_reduce<<<64, 256>>>(kvpp, kspp, kvh, kss);
    attn_mma<<<dim3(64, Tt / 128), 128>>>(Qh, kvh, kss, At);

    gemm_out<<<dim3(NCOL / 128, Mrows / 128), 256, SMEM_G>>>(At, Wt + 3 * WSZ, bo, out);
}